// round 2
// baseline (speedup 1.0000x reference)
#include <cuda_runtime.h>
#include <cuda_bf16.h>
#include <math.h>

// ---------------- problem constants ----------------
#define NN 10000
#define EE 160000
#define DN 256
#define DE 512
#define NH 8
#define DH 64
#define NC 10
#define KN 5000
#define KE 80000

// ---------------- device scratch (statics; no cudaMalloc allowed) ----------------
__device__ float g_q[(size_t)NN * DE];        // node queries [N,512]
__device__ float g_k[(size_t)EE * DE];        // edge keys; later reused as edge_feats
__device__ float g_v[(size_t)EE * DE];        // edge values; later reused as h (post-GELU)
__device__ float g_sc[(size_t)EE * NH];       // attention logits [E,8]
__device__ float g_agg[(size_t)NN * DE];      // per-node aggregated values [N,512]
__device__ float g_nscore[NN];
__device__ float g_escore[EE];
__device__ float g_nmask[NN];
__device__ float g_emask[EE];

// radix-select state
__device__ unsigned g_hist[256];
__device__ unsigned g_prefix;
__device__ unsigned g_krem;
__device__ float    g_thr[2];   // [0]=node thr, [1]=edge thr

// CSR
__device__ int g_deg[NN];
__device__ int g_off[NN + 1];
__device__ int g_cur[NN];
__device__ int g_elist[EE];

// ---------------- scorers: one warp per row ----------------
__global__ void score_kernel(const float* __restrict__ X, const float* __restrict__ w,
                             const float* __restrict__ b, float* __restrict__ out,
                             int M, int K)
{
    int warp = (blockIdx.x * blockDim.x + threadIdx.x) >> 5;
    int lane = threadIdx.x & 31;
    if (warp >= M) return;
    const float* row = X + (size_t)warp * K;
    float s = 0.f;
    for (int k = lane; k < K; k += 32) s += row[k] * w[k];
    #pragma unroll
    for (int o = 16; o; o >>= 1) s += __shfl_xor_sync(0xFFFFFFFFu, s, o);
    if (lane == 0) out[warp] = s + b[0];
}

// ---------------- exact k-th largest via 4x8-bit radix select ----------------
__device__ __forceinline__ unsigned f2u_ord(float x) {
    unsigned u = __float_as_uint(x);
    return (u & 0x80000000u) ? ~u : (u | 0x80000000u);
}

__global__ void rs_init(unsigned k) {
    if (threadIdx.x == 0) { g_prefix = 0u; g_krem = k; }
    g_hist[threadIdx.x] = 0u;  // launched with 256 threads
}

__global__ void rs_hist(const float* __restrict__ data, int n, int shift) {
    __shared__ unsigned sh[256];
    sh[threadIdx.x] = 0u;
    __syncthreads();
    unsigned prefix = g_prefix;
    unsigned maskhi = (shift == 24) ? 0u : (0xFFFFFFFFu << (shift + 8));
    for (int i = blockIdx.x * blockDim.x + threadIdx.x; i < n; i += gridDim.x * blockDim.x) {
        unsigned u = f2u_ord(data[i]);
        if ((u & maskhi) == prefix) atomicAdd(&sh[(u >> shift) & 255], 1u);
    }
    __syncthreads();
    unsigned c = sh[threadIdx.x];
    if (c) atomicAdd(&g_hist[threadIdx.x], c);
}

__global__ void rs_select(int shift, int thr_idx) {
    if (threadIdx.x == 0) {
        unsigned krem = g_krem, cum = 0; int digit = 0;
        for (int d = 255; d >= 0; d--) {
            unsigned c = g_hist[d];
            if (cum + c >= krem) { digit = d; break; }
            cum += c;
        }
        g_prefix |= ((unsigned)digit) << shift;
        g_krem = krem - cum;
        if (shift == 0) {
            unsigned u = g_prefix;
            u = (u & 0x80000000u) ? (u & 0x7FFFFFFFu) : ~u;
            g_thr[thr_idx] = __uint_as_float(u);
        }
    }
    __syncthreads();
    g_hist[threadIdx.x] = 0u;   // 256 threads
}

// ---------------- masks ----------------
__global__ void node_mask_kernel() {
    int i = blockIdx.x * blockDim.x + threadIdx.x;
    if (i < NN) g_nmask[i] = (g_nscore[i] >= g_thr[0]) ? 1.f : 0.f;
}
__global__ void edge_mask_kernel(const int* __restrict__ src, const int* __restrict__ dst) {
    int i = blockIdx.x * blockDim.x + threadIdx.x;
    if (i < EE) {
        bool m = (g_escore[i] >= g_thr[1]) && (g_nmask[src[i]] > 0.5f) && (g_nmask[dst[i]] > 0.5f);
        g_emask[i] = m ? 1.f : 0.f;
    }
}

// ---------------- CSR build ----------------
__global__ void zero_deg_kernel() {
    int i = blockIdx.x * blockDim.x + threadIdx.x;
    if (i < NN) g_deg[i] = 0;
}
__global__ void count_deg_kernel(const int* __restrict__ src) {
    int e = blockIdx.x * blockDim.x + threadIdx.x;
    if (e < EE) atomicAdd(&g_deg[src[e]], 1);
}
__global__ void scan_deg_kernel() {   // 1 block, 1024 threads
    __shared__ int part[1024];
    const int CH = (NN + 1023) / 1024;
    int t = threadIdx.x;
    int s = 0;
    for (int j = 0; j < CH; j++) { int i = t * CH + j; if (i < NN) s += g_deg[i]; }
    part[t] = s;
    __syncthreads();
    if (t == 0) {
        int run = 0;
        for (int i = 0; i < 1024; i++) { int v = part[i]; part[i] = run; run += v; }
        g_off[NN] = run;
    }
    __syncthreads();
    int run = part[t];
    for (int j = 0; j < CH; j++) {
        int i = t * CH + j;
        if (i < NN) { g_off[i] = run; g_cur[i] = run; run += g_deg[i]; }
    }
}
__global__ void scatter_kernel(const int* __restrict__ src) {
    int e = blockIdx.x * blockDim.x + threadIdx.x;
    if (e < EE) {
        int p = atomicAdd(&g_cur[src[e]], 1);
        g_elist[p] = e;
    }
}

// ---------------- tiled fp32 GEMM: C[M,512] = op(A)[M,K] @ B[K,512] + epi ----------------
// AMODE: 0 = plain A, 1 = row-mask-scaled A, 2 = row-gathered A
// EPI:   0 = +bias, 1 = +bias + rowmask*res, 2 = gelu(x+bias)
#define BM 128
#define BN 128
#define BK 16
template<int AMODE, int EPI>
__global__ __launch_bounds__(256)
void gemm_kernel(const float* __restrict__ A, const float* __restrict__ B,
                 const float* __restrict__ bias, float* __restrict__ C,
                 int M, int K,
                 const float* __restrict__ rowmask,
                 const int* __restrict__ gidx,
                 const float* __restrict__ resA)
{
    __shared__ float As[BK][BM];
    __shared__ float Bs[BK][BN];
    const int tid = threadIdx.x;
    const int row0 = blockIdx.y * BM;
    const int col0 = blockIdx.x * BN;
    const int tx = tid & 15, ty = tid >> 4;
    float acc[8][8];
    #pragma unroll
    for (int i = 0; i < 8; i++)
        #pragma unroll
        for (int j = 0; j < 8; j++) acc[i][j] = 0.f;

    for (int k0 = 0; k0 < K; k0 += BK) {
        #pragma unroll
        for (int it = 0; it < 2; it++) {
            int slot = tid + 256 * it;
            // A: 128 rows x 4 float4
            int arow = slot >> 2, ac4 = slot & 3;
            int gRow = row0 + arow;
            float4 av = make_float4(0.f, 0.f, 0.f, 0.f);
            if (gRow < M) {
                int srcRow = gRow;
                float f = 1.f;
                if (AMODE == 1) f = rowmask[gRow];
                if (AMODE == 2) srcRow = gidx[gRow];
                av = *reinterpret_cast<const float4*>(&A[(size_t)srcRow * K + k0 + ac4 * 4]);
                if (AMODE == 1) { av.x *= f; av.y *= f; av.z *= f; av.w *= f; }
            }
            As[ac4 * 4 + 0][arow] = av.x;
            As[ac4 * 4 + 1][arow] = av.y;
            As[ac4 * 4 + 2][arow] = av.z;
            As[ac4 * 4 + 3][arow] = av.w;
            // B: 16 rows x 32 float4
            int brow = slot >> 5, bc4 = slot & 31;
            float4 bv = *reinterpret_cast<const float4*>(&B[(size_t)(k0 + brow) * DE + col0 + bc4 * 4]);
            *reinterpret_cast<float4*>(&Bs[brow][bc4 * 4]) = bv;
        }
        __syncthreads();
        #pragma unroll
        for (int kk = 0; kk < BK; kk++) {
            float ar[8], br[8];
            #pragma unroll
            for (int i = 0; i < 8; i++) ar[i] = As[kk][ty * 8 + i];
            #pragma unroll
            for (int j = 0; j < 8; j++) br[j] = Bs[kk][tx * 8 + j];
            #pragma unroll
            for (int i = 0; i < 8; i++)
                #pragma unroll
                for (int j = 0; j < 8; j++)
                    acc[i][j] += ar[i] * br[j];
        }
        __syncthreads();
    }
    #pragma unroll
    for (int i = 0; i < 8; i++) {
        int gRow = row0 + ty * 8 + i;
        if (gRow >= M) continue;
        float f = (EPI == 1) ? rowmask[gRow] : 0.f;
        #pragma unroll
        for (int j = 0; j < 8; j++) {
            int gCol = col0 + tx * 8 + j;
            float v = acc[i][j] + bias[gCol];
            if (EPI == 1) v += f * resA[(size_t)gRow * DE + gCol];
            if (EPI == 2) v = 0.5f * v * (1.0f + erff(v * 0.70710678118654752f));
            C[(size_t)gRow * DE + gCol] = v;
        }
    }
}

// ---------------- attention logits: one warp per edge, 8 heads ----------------
__global__ void attn_scores_kernel(const int* __restrict__ src) {
    int warp = blockIdx.x * 8 + (threadIdx.x >> 5);
    int lane = threadIdx.x & 31;
    if (warp >= EE) return;
    int e = warp;
    const float4* qr = reinterpret_cast<const float4*>(g_q + (size_t)src[e] * DE);
    const float4* kr = reinterpret_cast<const float4*>(g_k + (size_t)e * DE);
    float s = 0.f;
    int base = lane * 4;   // 4 consecutive float4 = 16 floats, all within one head (64)
    #pragma unroll
    for (int j = 0; j < 4; j++) {
        float4 a = qr[base + j], b = kr[base + j];
        s += a.x * b.x + a.y * b.y + a.z * b.z + a.w * b.w;
    }
    s += __shfl_xor_sync(0xFFFFFFFFu, s, 1);
    s += __shfl_xor_sync(0xFFFFFFFFu, s, 2);
    if ((lane & 3) == 0) g_sc[(size_t)e * NH + (lane >> 2)] = s * 0.125f;  // 1/sqrt(64)
}

// ---------------- segment softmax + weighted aggregation: one block per node ----------------
__global__ void softmax_agg_kernel() {
    int n = blockIdx.x;
    int off = g_off[n];
    int deg = g_off[n + 1] - off;
    __shared__ float m_sh[NH], d_sh[NH];
    __shared__ float attn_sh[64 * NH];
    int tid = threadIdx.x;          // 256
    int wid = tid >> 5, lane = tid & 31;

    // pass 1: warp wid owns head wid — max and exp-sum over incident edges
    {
        float mx = -INFINITY;
        for (int i = lane; i < deg; i += 32) {
            int e = g_elist[off + i];
            mx = fmaxf(mx, g_sc[(size_t)e * NH + wid]);
        }
        #pragma unroll
        for (int o = 16; o; o >>= 1) mx = fmaxf(mx, __shfl_xor_sync(0xFFFFFFFFu, mx, o));
        float sm = 0.f;
        for (int i = lane; i < deg; i += 32) {
            int e = g_elist[off + i];
            sm += expf(g_sc[(size_t)e * NH + wid] - mx);
        }
        #pragma unroll
        for (int o = 16; o; o >>= 1) sm += __shfl_xor_sync(0xFFFFFFFFu, sm, o);
        if (lane == 0) { m_sh[wid] = mx; d_sh[wid] = sm; }
    }
    __syncthreads();

    // pass 2: chunked attn in shared, each thread owns 2 output dims
    float2 acc = make_float2(0.f, 0.f);
    int d0 = tid * 2;
    int h = d0 >> 6;
    for (int base = 0; base < deg; base += 64) {
        int cnt = min(64, deg - base);
        __syncthreads();
        for (int idx = tid; idx < cnt * NH; idx += 256) {
            int j = idx >> 3, hh = idx & 7;
            int e = g_elist[off + base + j];
            attn_sh[idx] = expf(g_sc[(size_t)e * NH + hh] - m_sh[hh]) / d_sh[hh];
        }
        __syncthreads();
        for (int j = 0; j < cnt; j++) {
            int e = g_elist[off + base + j];
            float a = attn_sh[j * NH + h];
            float2 vv = *reinterpret_cast<const float2*>(g_v + (size_t)e * DE + d0);
            acc.x += a * vv.x;
            acc.y += a * vv.y;
        }
    }
    *reinterpret_cast<float2*>(g_agg + (size_t)n * DE + d0) = acc;
}

// ---------------- classifier: one warp per edge, W2 in shared ----------------
__global__ void classify_kernel(const float* __restrict__ W2, const float* __restrict__ b2,
                                float* __restrict__ out) {
    __shared__ float W2s[DE * NC];
    int tid = threadIdx.x;   // 256
    for (int i = tid; i < DE * NC; i += 256) W2s[i] = W2[i];
    __syncthreads();
    int warp = blockIdx.x * 8 + (tid >> 5);
    if (warp >= EE) return;
    int lane = tid & 31;
    const float* hr = g_v + (size_t)warp * DE;   // g_v holds post-GELU h
    float p[NC];
    #pragma unroll
    for (int c = 0; c < NC; c++) p[c] = 0.f;
    for (int k = lane; k < DE; k += 32) {
        float hv = hr[k];
        const float* wk = &W2s[k * NC];
        #pragma unroll
        for (int c = 0; c < NC; c++) p[c] += hv * wk[c];
    }
    #pragma unroll
    for (int c = 0; c < NC; c++) {
        #pragma unroll
        for (int o = 16; o; o >>= 1) p[c] += __shfl_xor_sync(0xFFFFFFFFu, p[c], o);
    }
    if (lane == 0) {
        #pragma unroll
        for (int c = 0; c < NC; c++) out[(size_t)warp * NC + c] = p[c] + b2[c];
    }
}

// ---------------- host launcher ----------------
extern "C" void kernel_launch(void* const* d_in, const int* in_sizes, int n_in,
                              void* d_out, int out_size)
{
    const float* node_features = (const float*)d_in[0];
    const float* edge_features = (const float*)d_in[1];
    const int*   edge_index    = (const int*)d_in[2];
    const float* nw = (const float*)d_in[4];
    const float* nb = (const float*)d_in[5];
    const float* ew = (const float*)d_in[6];
    const float* eb = (const float*)d_in[7];
    const float* Wq = (const float*)d_in[8];  const float* bq = (const float*)d_in[9];
    const float* Wk = (const float*)d_in[10]; const float* bk = (const float*)d_in[11];
    const float* Wv = (const float*)d_in[12]; const float* bv = (const float*)d_in[13];
    const float* Wo = (const float*)d_in[14]; const float* bo = (const float*)d_in[15];
    const float* W1 = (const float*)d_in[16]; const float* b1 = (const float*)d_in[17];
    const float* W2 = (const float*)d_in[18]; const float* b2 = (const float*)d_in[19];
    float* out = (float*)d_out;
    const int* src = edge_index;
    const int* dst = edge_index + EE;

    float *qp, *kp, *vp, *aggp, *nsp, *esp, *emp;
    cudaGetSymbolAddress((void**)&qp,   g_q);
    cudaGetSymbolAddress((void**)&kp,   g_k);
    cudaGetSymbolAddress((void**)&vp,   g_v);
    cudaGetSymbolAddress((void**)&aggp, g_agg);
    cudaGetSymbolAddress((void**)&nsp,  g_nscore);
    cudaGetSymbolAddress((void**)&esp,  g_escore);
    cudaGetSymbolAddress((void**)&emp,  g_emask);

    // 1. linear scorers
    score_kernel<<<(NN + 7) / 8, 256>>>(node_features, nw, nb, nsp, NN, DN);
    score_kernel<<<(EE + 7) / 8, 256>>>(edge_features, ew, eb, esp, EE, DE);

    // 2. exact top-k thresholds (4-pass radix select on each score array)
    rs_init<<<1, 256>>>(KN);
    for (int shift = 24; shift >= 0; shift -= 8) {
        rs_hist<<<64, 256>>>(nsp, NN, shift);
        rs_select<<<1, 256>>>(shift, 0);
    }
    rs_init<<<1, 256>>>(KE);
    for (int shift = 24; shift >= 0; shift -= 8) {
        rs_hist<<<256, 256>>>(esp, EE, shift);
        rs_select<<<1, 256>>>(shift, 1);
    }

    // 3. masks
    node_mask_kernel<<<(NN + 255) / 256, 256>>>();
    edge_mask_kernel<<<(EE + 255) / 256, 256>>>(src, dst);

    // 4. CSR by source node
    zero_deg_kernel<<<(NN + 255) / 256, 256>>>();
    count_deg_kernel<<<(EE + 255) / 256, 256>>>(src);
    scan_deg_kernel<<<1, 1024>>>();
    scatter_kernel<<<(EE + 255) / 256, 256>>>(src);

    // 5. projections
    dim3 gq(DE / BN, (NN + BM - 1) / BM);
    gemm_kernel<0, 0><<<gq, 256>>>(node_features, Wq, bq, qp, NN, DN, nullptr, nullptr, nullptr);
    dim3 ge(DE / BN, (EE + BM - 1) / BM);
    gemm_kernel<1, 0><<<ge, 256>>>(edge_features, Wk, bk, kp, EE, DE, emp, nullptr, nullptr);
    gemm_kernel<1, 0><<<ge, 256>>>(edge_features, Wv, bv, vp, EE, DE, emp, nullptr, nullptr);

    // 6. attention logits, segment softmax + aggregation
    attn_scores_kernel<<<EE / 8, 256>>>(src);
    softmax_agg_kernel<<<NN, 256>>>();

    // 7. output projection + residual (A = agg gathered by src) -> reuse g_k as edge_feats
    gemm_kernel<2, 1><<<ge, 256>>>(aggp, Wo, bo, kp, EE, DE, emp, src, edge_features);

    // 8. MLP hidden with exact GELU -> reuse g_v as h
    gemm_kernel<0, 2><<<ge, 256>>>(kp, W1, b1, vp, EE, DE, nullptr, nullptr, nullptr);

    // 9. classifier head
    classify_kernel<<<EE / 8, 256>>>(W2, b2, out);
}

// round 4
// speedup vs baseline: 1.8929x; 1.8929x over previous
#include <cuda_runtime.h>
#include <cuda_bf16.h>
#include <math.h>
#include <stdint.h>

// ---------------- problem constants ----------------
#define NN 10000
#define EE 160000
#define DN 256
#define DE 512
#define NH 8
#define NC 10
#define KN 5000
#define KE 80000

// ---------------- device scratch ----------------
__device__ float g_q[(size_t)NN * DE];
__device__ float g_k[(size_t)EE * DE];        // keys; later reused as edge_feats
__device__ float g_v[(size_t)EE * DE];        // values; later reused as h
__device__ float g_sc[(size_t)EE * NH];
__device__ float g_agg[(size_t)NN * DE];
__device__ float g_nscore[NN];
__device__ float g_escore[EE];
__device__ float g_nmask[NN];
__device__ float g_emask[EE];
// bf16-split transposed weights: slot 0=Wq,1=Wk,2=Wv,3=Wo,4=W1  ([Nout=512, K] K-major)
__device__ __nv_bfloat16 g_whi[5][DE * DE];
__device__ __nv_bfloat16 g_wlo[5][DE * DE];

// radix-select state
__device__ unsigned g_hist[256];
__device__ unsigned g_prefix;
__device__ unsigned g_krem;
__device__ float    g_thr[2];

// CSR
__device__ int g_deg[NN];
__device__ int g_off[NN + 1];
__device__ int g_cur[NN];
__device__ int g_elist[EE];

// ================= PTX helpers (sm_80-era, valid on compute_100) =================
__device__ __forceinline__ void ldm4(uint32_t* r, uint32_t a) {
    asm volatile("ldmatrix.sync.aligned.m8n8.x4.shared.b16 {%0,%1,%2,%3}, [%4];"
                 : "=r"(r[0]), "=r"(r[1]), "=r"(r[2]), "=r"(r[3]) : "r"(a));
}
__device__ __forceinline__ void mma_bf16(float* d, const uint32_t* a, uint32_t b0, uint32_t b1) {
    asm volatile("mma.sync.aligned.m16n8k16.row.col.f32.bf16.bf16.f32 "
                 "{%0,%1,%2,%3},{%4,%5,%6,%7},{%8,%9},{%0,%1,%2,%3};"
                 : "+f"(d[0]), "+f"(d[1]), "+f"(d[2]), "+f"(d[3])
                 : "r"(a[0]), "r"(a[1]), "r"(a[2]), "r"(a[3]), "r"(b0), "r"(b1));
}
__device__ __forceinline__ void cpasync16(uint32_t s, const void* g) {
    asm volatile("cp.async.cg.shared.global [%0], [%1], 16;" :: "r"(s), "l"(g));
}
__device__ __forceinline__ void cp_commit() { asm volatile("cp.async.commit_group;" ::: "memory"); }
__device__ __forceinline__ void cp_wait0() { asm volatile("cp.async.wait_group 0;" ::: "memory"); }

__device__ __forceinline__ uint32_t pack2bf(float x, float y) {
    __nv_bfloat162 h = __floats2bfloat162_rn(x, y);
    return *reinterpret_cast<uint32_t*>(&h);
}

// ================= scorers: one warp per row =================
__global__ void score_kernel(const float* __restrict__ X, const float* __restrict__ w,
                             const float* __restrict__ b, float* __restrict__ out,
                             int M, int K)
{
    int warp = (blockIdx.x * blockDim.x + threadIdx.x) >> 5;
    int lane = threadIdx.x & 31;
    if (warp >= M) return;
    const float* row = X + (size_t)warp * K;
    float s = 0.f;
    for (int k = lane; k < K; k += 32) s += row[k] * w[k];
    #pragma unroll
    for (int o = 16; o; o >>= 1) s += __shfl_xor_sync(0xFFFFFFFFu, s, o);
    if (lane == 0) out[warp] = s + b[0];
}

// ================= exact top-k via 4x8-bit radix select =================
__device__ __forceinline__ unsigned f2u_ord(float x) {
    unsigned u = __float_as_uint(x);
    return (u & 0x80000000u) ? ~u : (u | 0x80000000u);
}
__global__ void rs_init(unsigned k) {
    if (threadIdx.x == 0) { g_prefix = 0u; g_krem = k; }
    g_hist[threadIdx.x] = 0u;
}
__global__ void rs_hist(const float* __restrict__ data, int n, int shift) {
    __shared__ unsigned sh[256];
    sh[threadIdx.x] = 0u;
    __syncthreads();
    unsigned prefix = g_prefix;
    unsigned maskhi = (shift == 24) ? 0u : (0xFFFFFFFFu << (shift + 8));
    for (int i = blockIdx.x * blockDim.x + threadIdx.x; i < n; i += gridDim.x * blockDim.x) {
        unsigned u = f2u_ord(data[i]);
        if ((u & maskhi) == prefix) atomicAdd(&sh[(u >> shift) & 255], 1u);
    }
    __syncthreads();
    unsigned c = sh[threadIdx.x];
    if (c) atomicAdd(&g_hist[threadIdx.x], c);
}
__global__ void rs_select(int shift, int thr_idx) {
    if (threadIdx.x == 0) {
        unsigned krem = g_krem, cum = 0; int digit = 0;
        for (int d = 255; d >= 0; d--) {
            unsigned c = g_hist[d];
            if (cum + c >= krem) { digit = d; break; }
            cum += c;
        }
        g_prefix |= ((unsigned)digit) << shift;
        g_krem = krem - cum;
        if (shift == 0) {
            unsigned u = g_prefix;
            u = (u & 0x80000000u) ? (u & 0x7FFFFFFFu) : ~u;
            g_thr[thr_idx] = __uint_as_float(u);
        }
    }
    __syncthreads();
    g_hist[threadIdx.x] = 0u;
}

// ================= masks =================
__global__ void node_mask_kernel() {
    int i = blockIdx.x * blockDim.x + threadIdx.x;
    if (i < NN) g_nmask[i] = (g_nscore[i] >= g_thr[0]) ? 1.f : 0.f;
}
__global__ void edge_mask_kernel(const int* __restrict__ src, const int* __restrict__ dst) {
    int i = blockIdx.x * blockDim.x + threadIdx.x;
    if (i < EE) {
        bool m = (g_escore[i] >= g_thr[1]) && (g_nmask[src[i]] > 0.5f) && (g_nmask[dst[i]] > 0.5f);
        g_emask[i] = m ? 1.f : 0.f;
    }
}

// ================= CSR build =================
__global__ void zero_deg_kernel() {
    int i = blockIdx.x * blockDim.x + threadIdx.x;
    if (i < NN) g_deg[i] = 0;
}
__global__ void count_deg_kernel(const int* __restrict__ src) {
    int e = blockIdx.x * blockDim.x + threadIdx.x;
    if (e < EE) atomicAdd(&g_deg[src[e]], 1);
}
__global__ void scan_deg_kernel() {
    __shared__ int part[1024];
    const int CH = (NN + 1023) / 1024;
    int t = threadIdx.x;
    int s = 0;
    for (int j = 0; j < CH; j++) { int i = t * CH + j; if (i < NN) s += g_deg[i]; }
    part[t] = s;
    __syncthreads();
    if (t == 0) {
        int run = 0;
        for (int i = 0; i < 1024; i++) { int v = part[i]; part[i] = run; run += v; }
        g_off[NN] = run;
    }
    __syncthreads();
    int run = part[t];
    for (int j = 0; j < CH; j++) {
        int i = t * CH + j;
        if (i < NN) { g_off[i] = run; g_cur[i] = run; run += g_deg[i]; }
    }
}
__global__ void scatter_kernel(const int* __restrict__ src) {
    int e = blockIdx.x * blockDim.x + threadIdx.x;
    if (e < EE) {
        int p = atomicAdd(&g_cur[src[e]], 1);
        g_elist[p] = e;
    }
}

// ================= weight transpose + bf16 hi/lo split =================
// W: [K, DE] row-major fp32 -> Whi/Wlo: [DE, K] row-major bf16 (K-major)
__global__ void wconv_kernel(const float* __restrict__ W, __nv_bfloat16* __restrict__ hi,
                             __nv_bfloat16* __restrict__ lo, int K)
{
    int idx = blockIdx.x * blockDim.x + threadIdx.x;
    if (idx >= DE * K) return;
    int n = idx % DE, k = idx / DE;
    float x = W[(size_t)k * DE + n];
    __nv_bfloat16 h = __float2bfloat16(x);
    hi[(size_t)n * K + k] = h;
    lo[(size_t)n * K + k] = __float2bfloat16(x - __bfloat162float(h));
}

// ================= mma.sync bf16-split GEMM =================
// C[M,512] = op(A)[M,K] @ W^T + epi, 3-pass bf16 hi/lo split.
// Tile 128x128, K-chunk 64. 8 warps (2x4), warp tile 64x32, m16n8k16 atoms.
// SMEM per stage: Ahi 16K | Alo 16K | Bhi 16K | Blo 16K. Two stages = 128KB.
// AMODE: 0 plain, 1 row-mask, 2 row-gather ; EPI: 0 +bias, 1 +bias+mask*res, 2 gelu(x+bias)
#define STAGE_BYTES 65536
#define GEMM_SMEM (2 * STAGE_BYTES)

template<int AMODE, int EPI>
__global__ __launch_bounds__(256, 1)
void mma_gemm(const float* __restrict__ A,
              const __nv_bfloat16* __restrict__ Bhi, const __nv_bfloat16* __restrict__ Blo,
              const float* __restrict__ bias, float* __restrict__ C,
              int M, int K,
              const float* __restrict__ rowmask, const int* __restrict__ gidx,
              const float* __restrict__ resA)
{
    extern __shared__ char sm[];
    const uint32_t sbase = (uint32_t)__cvta_generic_to_shared(sm);
    const int tid = threadIdx.x;
    const int w = tid >> 5, l = tid & 31;
    const int row0 = blockIdx.y * 128;
    const int n0 = blockIdx.x * 128;
    const int wm = w >> 2, wn = w & 3;

    float acc[4][4][4];
    #pragma unroll
    for (int i = 0; i < 4; i++)
        #pragma unroll
        for (int j = 0; j < 4; j++)
            #pragma unroll
            for (int p = 0; p < 4; p++) acc[i][j][p] = 0.f;

    const int ar = tid >> 1, ahalf = tid & 1;       // A tile: row + 32-float half
    const int agrow = row0 + ar;

    // ---- A: global load (fp32) into regs ----
    float4 areg[8];
    auto aload = [&](int k0) {
        if (agrow < M) {
            int sr = agrow;
            float f = 1.f;
            if (AMODE == 1) f = rowmask[agrow];
            if (AMODE == 2) sr = gidx[agrow];
            const float4* p = reinterpret_cast<const float4*>(A + (size_t)sr * K + k0 + ahalf * 32);
            #pragma unroll
            for (int j = 0; j < 8; j++) areg[j] = p[j];
            if (AMODE == 1) {
                #pragma unroll
                for (int j = 0; j < 8; j++) { areg[j].x *= f; areg[j].y *= f; areg[j].z *= f; areg[j].w *= f; }
            }
        } else {
            #pragma unroll
            for (int j = 0; j < 8; j++) areg[j] = make_float4(0.f, 0.f, 0.f, 0.f);
        }
    };
    // ---- A: convert hi/lo + swizzled STS ----
    auto astore = [&](int stage) {
        char* base = sm + stage * STAGE_BYTES + ar * 128;
        #pragma unroll
        for (int j2 = 0; j2 < 4; j2++) {
            float xs[8];
            float4 u = areg[j2 * 2], v = areg[j2 * 2 + 1];
            xs[0] = u.x; xs[1] = u.y; xs[2] = u.z; xs[3] = u.w;
            xs[4] = v.x; xs[5] = v.y; xs[6] = v.z; xs[7] = v.w;
            uint4 hv, lv;
            uint32_t* hp = &hv.x; uint32_t* lp = &lv.x;
            #pragma unroll
            for (int p = 0; p < 4; p++) {
                float a0 = xs[2 * p], a1 = xs[2 * p + 1];
                __nv_bfloat162 hh = __floats2bfloat162_rn(a0, a1);
                float r0 = a0 - __bfloat162float(hh.x);
                float r1 = a1 - __bfloat162float(hh.y);
                hp[p] = *reinterpret_cast<uint32_t*>(&hh);
                lp[p] = pack2bf(r0, r1);
            }
            int chunk = ahalf * 4 + j2;
            uint32_t swz = (uint32_t)((chunk ^ (ar & 7)) * 16);
            *reinterpret_cast<uint4*>(base + swz) = hv;
            *reinterpret_cast<uint4*>(base + 16384 + swz) = lv;
        }
    };
    // ---- B: cp.async pre-split bf16 with swizzle ----
    auto bload = [&](int k0, int stage) {
        uint32_t sb = sbase + stage * STAGE_BYTES + 32768;
        #pragma unroll
        for (int i = 0; i < 4; i++) {
            int lin = tid + 256 * i;
            int r = lin >> 3, ch = lin & 7;
            uint32_t so = sb + r * 128 + (uint32_t)((ch ^ (r & 7)) * 16);
            size_t gi = (size_t)(n0 + r) * K + k0 + ch * 8;
            cpasync16(so, &Bhi[gi]);
            cpasync16(so + 16384, &Blo[gi]);
        }
    };
    // ---- compute one stage: 4 k16-steps x 3 split passes ----
    auto compute = [&](int stage) {
        uint32_t ab = sbase + stage * STAGE_BYTES;
        uint32_t bb = ab + 32768;
        #pragma unroll
        for (int ks = 0; ks < 4; ks++) {
            int kc = ks * 2;
            uint32_t ahi[4][4], alo[4][4];
            #pragma unroll
            for (int mf = 0; mf < 4; mf++) {
                int rr = wm * 64 + mf * 16 + (l & 15);
                int kch = kc + (l >> 4);
                uint32_t addr = ab + rr * 128 + (uint32_t)(((kch ^ (rr & 7))) * 16);
                ldm4(ahi[mf], addr);
                ldm4(alo[mf], addr + 16384);
            }
            uint32_t bhi[2][4], blo[2][4];
            #pragma unroll
            for (int ng = 0; ng < 2; ng++) {
                int nr = wn * 32 + ng * 16 + (l & 7) + ((l >> 4) << 3);
                int kch = kc + ((l >> 3) & 1);
                uint32_t addr = bb + nr * 128 + (uint32_t)(((kch ^ (nr & 7))) * 16);
                ldm4(bhi[ng], addr);
                ldm4(blo[ng], addr + 16384);
            }
            #pragma unroll
            for (int mf = 0; mf < 4; mf++) {
                #pragma unroll
                for (int nf = 0; nf < 4; nf++) {
                    int ng = nf >> 1, sb2 = (nf & 1) * 2;
                    mma_bf16(acc[mf][nf], ahi[mf], bhi[ng][sb2], bhi[ng][sb2 + 1]);
                    mma_bf16(acc[mf][nf], ahi[mf], blo[ng][sb2], blo[ng][sb2 + 1]);
                    mma_bf16(acc[mf][nf], alo[mf], bhi[ng][sb2], bhi[ng][sb2 + 1]);
                }
            }
        }
    };

    // ---- pipeline ----
    const int nch = K >> 6;
    aload(0);
    astore(0);
    bload(0, 0);
    cp_commit();
    for (int c = 0; c < nch; c++) {
        int cur = c & 1;
        bool hn = (c + 1 < nch);
        if (hn) aload((c + 1) * 64);
        cp_wait0();
        __syncthreads();
        if (hn) { bload((c + 1) * 64, cur ^ 1); cp_commit(); }
        compute(cur);
        if (hn) astore(cur ^ 1);
    }

    // ---- epilogue ----
    #pragma unroll
    for (int mf = 0; mf < 4; mf++) {
        int gr0 = row0 + wm * 64 + mf * 16 + (l >> 2);
        #pragma unroll
        for (int nf = 0; nf < 4; nf++) {
            int gc = n0 + wn * 32 + nf * 8 + (l & 3) * 2;
            #pragma unroll
            for (int h = 0; h < 2; h++) {
                int grow = gr0 + 8 * h;
                if (grow >= M) continue;
                float v0 = acc[mf][nf][2 * h] + bias[gc];
                float v1 = acc[mf][nf][2 * h + 1] + bias[gc + 1];
                if (EPI == 1) {
                    float f = rowmask[grow];
                    v0 += f * resA[(size_t)grow * DE + gc];
                    v1 += f * resA[(size_t)grow * DE + gc + 1];
                }
                if (EPI == 2) {
                    v0 = 0.5f * v0 * (1.0f + erff(v0 * 0.70710678118654752f));
                    v1 = 0.5f * v1 * (1.0f + erff(v1 * 0.70710678118654752f));
                }
                *reinterpret_cast<float2*>(&C[(size_t)grow * DE + gc]) = make_float2(v0, v1);
            }
        }
    }
}

// ================= attention logits: one warp per edge =================
__global__ void attn_scores_kernel(const int* __restrict__ src) {
    int warp = blockIdx.x * 8 + (threadIdx.x >> 5);
    int lane = threadIdx.x & 31;
    if (warp >= EE) return;
    int e = warp;
    const float4* qr = reinterpret_cast<const float4*>(g_q + (size_t)src[e] * DE);
    const float4* kr = reinterpret_cast<const float4*>(g_k + (size_t)e * DE);
    float s = 0.f;
    int base = lane * 4;
    #pragma unroll
    for (int j = 0; j < 4; j++) {
        float4 a = qr[base + j], b = kr[base + j];
        s += a.x * b.x + a.y * b.y + a.z * b.z + a.w * b.w;
    }
    s += __shfl_xor_sync(0xFFFFFFFFu, s, 1);
    s += __shfl_xor_sync(0xFFFFFFFFu, s, 2);
    if ((lane & 3) == 0) g_sc[(size_t)e * NH + (lane >> 2)] = s * 0.125f;
}

// ================= segment softmax + aggregation: one block per node =================
__global__ void softmax_agg_kernel() {
    int n = blockIdx.x;
    int off = g_off[n];
    int deg = g_off[n + 1] - off;
    __shared__ float m_sh[NH], d_sh[NH];
    __shared__ float attn_sh[64 * NH];
    int tid = threadIdx.x;
    int wid = tid >> 5, lane = tid & 31;
    {
        float mx = -INFINITY;
        for (int i = lane; i < deg; i += 32) {
            int e = g_elist[off + i];
            mx = fmaxf(mx, g_sc[(size_t)e * NH + wid]);
        }
        #pragma unroll
        for (int o = 16; o; o >>= 1) mx = fmaxf(mx, __shfl_xor_sync(0xFFFFFFFFu, mx, o));
        float sm = 0.f;
        for (int i = lane; i < deg; i += 32) {
            int e = g_elist[off + i];
            sm += expf(g_sc[(size_t)e * NH + wid] - mx);
        }
        #pragma unroll
        for (int o = 16; o; o >>= 1) sm += __shfl_xor_sync(0xFFFFFFFFu, sm, o);
        if (lane == 0) { m_sh[wid] = mx; d_sh[wid] = sm; }
    }
    __syncthreads();
    float2 acc = make_float2(0.f, 0.f);
    int d0 = tid * 2;
    int h = d0 >> 6;
    for (int base = 0; base < deg; base += 64) {
        int cnt = min(64, deg - base);
        __syncthreads();
        for (int idx = tid; idx < cnt * NH; idx += 256) {
            int j = idx >> 3, hh = idx & 7;
            int e = g_elist[off + base + j];
            attn_sh[idx] = expf(g_sc[(size_t)e * NH + hh] - m_sh[hh]) / d_sh[hh];
        }
        __syncthreads();
        for (int j = 0; j < cnt; j++) {
            int e = g_elist[off + base + j];
            float a = attn_sh[j * NH + h];
            float2 vv = *reinterpret_cast<const float2*>(g_v + (size_t)e * DE + d0);
            acc.x += a * vv.x;
            acc.y += a * vv.y;
        }
    }
    *reinterpret_cast<float2*>(g_agg + (size_t)n * DE + d0) = acc;
}

// ================= classifier: one warp per edge =================
__global__ void classify_kernel(const float* __restrict__ W2, const float* __restrict__ b2,
                                float* __restrict__ out) {
    __shared__ float W2s[DE * NC];
    int tid = threadIdx.x;
    for (int i = tid; i < DE * NC; i += 256) W2s[i] = W2[i];
    __syncthreads();
    int warp = blockIdx.x * 8 + (tid >> 5);
    if (warp >= EE) return;
    int lane = tid & 31;
    const float* hr = g_v + (size_t)warp * DE;
    float p[NC];
    #pragma unroll
    for (int c = 0; c < NC; c++) p[c] = 0.f;
    for (int k = lane; k < DE; k += 32) {
        float hv = hr[k];
        const float* wk = &W2s[k * NC];
        #pragma unroll
        for (int c = 0; c < NC; c++) p[c] += hv * wk[c];
    }
    #pragma unroll
    for (int c = 0; c < NC; c++) {
        #pragma unroll
        for (int o = 16; o; o >>= 1) p[c] += __shfl_xor_sync(0xFFFFFFFFu, p[c], o);
    }
    if (lane == 0) {
        #pragma unroll
        for (int c = 0; c < NC; c++) out[(size_t)warp * NC + c] = p[c] + b2[c];
    }
}

// ================= host launcher =================
extern "C" void kernel_launch(void* const* d_in, const int* in_sizes, int n_in,
                              void* d_out, int out_size)
{
    const float* node_features = (const float*)d_in[0];
    const float* edge_features = (const float*)d_in[1];
    const int*   edge_index    = (const int*)d_in[2];
    const float* nw = (const float*)d_in[4];
    const float* nb = (const float*)d_in[5];
    const float* ew = (const float*)d_in[6];
    const float* eb = (const float*)d_in[7];
    const float* Wq = (const float*)d_in[8];  const float* bq = (const float*)d_in[9];
    const float* Wk = (const float*)d_in[10]; const float* bk = (const float*)d_in[11];
    const float* Wv = (const float*)d_in[12]; const float* bv = (const float*)d_in[13];
    const float* Wo = (const float*)d_in[14]; const float* bo = (const float*)d_in[15];
    const float* W1 = (const float*)d_in[16]; const float* b1 = (const float*)d_in[17];
    const float* W2 = (const float*)d_in[18]; const float* b2 = (const float*)d_in[19];
    float* out = (float*)d_out;
    const int* src = edge_index;
    const int* dst = edge_index + EE;

    float *qp, *kp, *vp, *aggp, *nsp, *esp, *emp;
    __nv_bfloat16 *whi, *wlo;
    cudaGetSymbolAddress((void**)&qp,   g_q);
    cudaGetSymbolAddress((void**)&kp,   g_k);
    cudaGetSymbolAddress((void**)&vp,   g_v);
    cudaGetSymbolAddress((void**)&aggp, g_agg);
    cudaGetSymbolAddress((void**)&nsp,  g_nscore);
    cudaGetSymbolAddress((void**)&esp,  g_escore);
    cudaGetSymbolAddress((void**)&emp,  g_emask);
    cudaGetSymbolAddress((void**)&whi,  g_whi);
    cudaGetSymbolAddress((void**)&wlo,  g_wlo);

    cudaFuncSetAttribute((const void*)mma_gemm<0,0>, cudaFuncAttributeMaxDynamicSharedMemorySize, GEMM_SMEM);
    cudaFuncSetAttribute((const void*)mma_gemm<1,0>, cudaFuncAttributeMaxDynamicSharedMemorySize, GEMM_SMEM);
    cudaFuncSetAttribute((const void*)mma_gemm<2,1>, cudaFuncAttributeMaxDynamicSharedMemorySize, GEMM_SMEM);
    cudaFuncSetAttribute((const void*)mma_gemm<0,2>, cudaFuncAttributeMaxDynamicSharedMemorySize, GEMM_SMEM);

    // 0. weight transpose + bf16 split (slots: 0=Wq K=256, 1=Wk, 2=Wv, 3=Wo, 4=W1)
    wconv_kernel<<<(DE * DN + 255) / 256, 256>>>(Wq, whi + 0 * (size_t)DE * DE, wlo + 0 * (size_t)DE * DE, DN);
    wconv_kernel<<<(DE * DE + 255) / 256, 256>>>(Wk, whi + 1 * (size_t)DE * DE, wlo + 1 * (size_t)DE * DE, DE);
    wconv_kernel<<<(DE * DE + 255) / 256, 256>>>(Wv, whi + 2 * (size_t)DE * DE, wlo + 2 * (size_t)DE * DE, DE);
    wconv_kernel<<<(DE * DE + 255) / 256, 256>>>(Wo, whi + 3 * (size_t)DE * DE, wlo + 3 * (size_t)DE * DE, DE);
    wconv_kernel<<<(DE * DE + 255) / 256, 256>>>(W1, whi + 4 * (size_t)DE * DE, wlo + 4 * (size_t)DE * DE, DE);

    // 1. linear scorers (exact fp32 -> masks stay bit-exact)
    score_kernel<<<(NN + 7) / 8, 256>>>(node_features, nw, nb, nsp, NN, DN);
    score_kernel<<<(EE + 7) / 8, 256>>>(edge_features, ew, eb, esp, EE, DE);

    // 2. exact top-k thresholds
    rs_init<<<1, 256>>>(KN);
    for (int shift = 24; shift >= 0; shift -= 8) {
        rs_hist<<<64, 256>>>(nsp, NN, shift);
        rs_select<<<1, 256>>>(shift, 0);
    }
    rs_init<<<1, 256>>>(KE);
    for (int shift = 24; shift >= 0; shift -= 8) {
        rs_hist<<<256, 256>>>(esp, EE, shift);
        rs_select<<<1, 256>>>(shift, 1);
    }

    // 3. masks
    node_mask_kernel<<<(NN + 255) / 256, 256>>>();
    edge_mask_kernel<<<(EE + 255) / 256, 256>>>(src, dst);

    // 4. CSR by source node
    zero_deg_kernel<<<(NN + 255) / 256, 256>>>();
    count_deg_kernel<<<(EE + 255) / 256, 256>>>(src);
    scan_deg_kernel<<<1, 1024>>>();
    scatter_kernel<<<(EE + 255) / 256, 256>>>(src);

    // 5. projections (mma.sync bf16-split)
    dim3 gq(4, (NN + 127) / 128);
    mma_gemm<0,0><<<gq, 256, GEMM_SMEM>>>(node_features, whi + 0 * (size_t)DE * DE, wlo + 0 * (size_t)DE * DE,
                                          bq, qp, NN, DN, nullptr, nullptr, nullptr);
    dim3 ge(4, EE / 128);
    mma_gemm<1,0><<<ge, 256, GEMM_SMEM>>>(edge_features, whi + 1 * (size_t)DE * DE, wlo + 1 * (size_t)DE * DE,
                                          bk, kp, EE, DE, emp, nullptr, nullptr);
    mma_gemm<1,0><<<ge, 256, GEMM_SMEM>>>(edge_features, whi + 2 * (size_t)DE * DE, wlo + 2 * (size_t)DE * DE,
                                          bv, vp, EE, DE, emp, nullptr, nullptr);

    // 6. attention logits, segment softmax + aggregation
    attn_scores_kernel<<<EE / 8, 256>>>(src);
    softmax_agg_kernel<<<NN, 256>>>();

    // 7. output projection + residual (gather agg[src]) -> g_k becomes edge_feats
    mma_gemm<2,1><<<ge, 256, GEMM_SMEM>>>(aggp, whi + 3 * (size_t)DE * DE, wlo + 3 * (size_t)DE * DE,
                                          bo, kp, EE, DE, emp, src, edge_features);

    // 8. MLP hidden + exact GELU -> g_v becomes h
    mma_gemm<0,2><<<ge, 256, GEMM_SMEM>>>(kp, whi + 4 * (size_t)DE * DE, wlo + 4 * (size_t)DE * DE,
                                          b1, vp, EE, DE, nullptr, nullptr, nullptr);

    // 9. classifier head
    classify_kernel<<<EE / 8, 256>>>(W2, b2, out);
}

// round 5
// speedup vs baseline: 2.2884x; 1.2089x over previous
#include <cuda_runtime.h>
#include <cuda_bf16.h>
#include <math.h>
#include <stdint.h>

// ---------------- problem constants ----------------
#define NN 10000
#define EE 160000
#define DN 256
#define DE 512
#define NH 8
#define NC 10
#define KN 5000
#define KE 80000

// ---------------- device scratch ----------------
__device__ float g_q[(size_t)NN * DE];
__device__ float g_k[(size_t)EE * DE];        // keys
__device__ float g_v[(size_t)EE * DE];        // values; later reused as h (post-GELU)
__device__ float g_sc[(size_t)EE * NH];
__device__ float g_agg[(size_t)NN * DE];
__device__ float g_nscore[NN];
__device__ float g_escore[EE];
__device__ float g_nmask[NN];
__device__ float g_emask[EE];
// bf16 hi/lo splits of GEMM A-operands
__device__ __nv_bfloat16 g_efhi[(size_t)EE * DE];   // edge_features split; reused for hidden
__device__ __nv_bfloat16 g_eflo[(size_t)EE * DE];
__device__ __nv_bfloat16 g_nfhi[(size_t)NN * DN];
__device__ __nv_bfloat16 g_nflo[(size_t)NN * DN];
__device__ __nv_bfloat16 g_agghi[(size_t)NN * DE];
__device__ __nv_bfloat16 g_agglo[(size_t)NN * DE];
// bf16-split transposed weights: slot 0=Wq,1=Wk,2=Wv,3=Wo,4=W1  ([Nout=512, K] K-major)
__device__ __nv_bfloat16 g_whi[5][DE * DE];
__device__ __nv_bfloat16 g_wlo[5][DE * DE];

// radix-select state
__device__ unsigned g_hist[256];
__device__ unsigned g_prefix;
__device__ unsigned g_krem;
__device__ float    g_thr[2];

// CSR
__device__ int g_deg[NN];
__device__ int g_off[NN + 1];
__device__ int g_cur[NN];
__device__ int g_elist[EE];

// ================= PTX helpers =================
__device__ __forceinline__ void ldm4(uint32_t* r, uint32_t a) {
    asm volatile("ldmatrix.sync.aligned.m8n8.x4.shared.b16 {%0,%1,%2,%3}, [%4];"
                 : "=r"(r[0]), "=r"(r[1]), "=r"(r[2]), "=r"(r[3]) : "r"(a));
}
__device__ __forceinline__ void mma_bf16(float* d, const uint32_t* a, uint32_t b0, uint32_t b1) {
    asm volatile("mma.sync.aligned.m16n8k16.row.col.f32.bf16.bf16.f32 "
                 "{%0,%1,%2,%3},{%4,%5,%6,%7},{%8,%9},{%0,%1,%2,%3};"
                 : "+f"(d[0]), "+f"(d[1]), "+f"(d[2]), "+f"(d[3])
                 : "r"(a[0]), "r"(a[1]), "r"(a[2]), "r"(a[3]), "r"(b0), "r"(b1));
}
__device__ __forceinline__ void cpasync16(uint32_t s, const void* g) {
    asm volatile("cp.async.cg.shared.global [%0], [%1], 16;" :: "r"(s), "l"(g));
}
__device__ __forceinline__ void cp_commit() { asm volatile("cp.async.commit_group;" ::: "memory"); }
#define CP_WAIT(n) asm volatile("cp.async.wait_group %0;" :: "n"(n) : "memory")

__device__ __forceinline__ uint32_t pack2bf(float x, float y) {
    __nv_bfloat162 h = __floats2bfloat162_rn(x, y);
    return *reinterpret_cast<uint32_t*>(&h);
}

// ================= scorers: one warp per row =================
__global__ void score_kernel(const float* __restrict__ X, const float* __restrict__ w,
                             const float* __restrict__ b, float* __restrict__ out,
                             int M, int K)
{
    int warp = (blockIdx.x * blockDim.x + threadIdx.x) >> 5;
    int lane = threadIdx.x & 31;
    if (warp >= M) return;
    const float* row = X + (size_t)warp * K;
    float s = 0.f;
    for (int k = lane; k < K; k += 32) s += row[k] * w[k];
    #pragma unroll
    for (int o = 16; o; o >>= 1) s += __shfl_xor_sync(0xFFFFFFFFu, s, o);
    if (lane == 0) out[warp] = s + b[0];
}

// ================= exact top-k via 4x8-bit radix select =================
__device__ __forceinline__ unsigned f2u_ord(float x) {
    unsigned u = __float_as_uint(x);
    return (u & 0x80000000u) ? ~u : (u | 0x80000000u);
}
__global__ void rs_init(unsigned k) {
    if (threadIdx.x == 0) { g_prefix = 0u; g_krem = k; }
    g_hist[threadIdx.x] = 0u;
}
__global__ void rs_hist(const float* __restrict__ data, int n, int shift) {
    __shared__ unsigned sh[256];
    sh[threadIdx.x] = 0u;
    __syncthreads();
    unsigned prefix = g_prefix;
    unsigned maskhi = (shift == 24) ? 0u : (0xFFFFFFFFu << (shift + 8));
    for (int i = blockIdx.x * blockDim.x + threadIdx.x; i < n; i += gridDim.x * blockDim.x) {
        unsigned u = f2u_ord(data[i]);
        if ((u & maskhi) == prefix) atomicAdd(&sh[(u >> shift) & 255], 1u);
    }
    __syncthreads();
    unsigned c = sh[threadIdx.x];
    if (c) atomicAdd(&g_hist[threadIdx.x], c);
}
__global__ void rs_select(int shift, int thr_idx) {
    if (threadIdx.x == 0) {
        unsigned krem = g_krem, cum = 0; int digit = 0;
        for (int d = 255; d >= 0; d--) {
            unsigned c = g_hist[d];
            if (cum + c >= krem) { digit = d; break; }
            cum += c;
        }
        g_prefix |= ((unsigned)digit) << shift;
        g_krem = krem - cum;
        if (shift == 0) {
            unsigned u = g_prefix;
            u = (u & 0x80000000u) ? (u & 0x7FFFFFFFu) : ~u;
            g_thr[thr_idx] = __uint_as_float(u);
        }
    }
    __syncthreads();
    g_hist[threadIdx.x] = 0u;
}

// ================= masks =================
__global__ void node_mask_kernel() {
    int i = blockIdx.x * blockDim.x + threadIdx.x;
    if (i < NN) g_nmask[i] = (g_nscore[i] >= g_thr[0]) ? 1.f : 0.f;
}
__global__ void edge_mask_kernel(const int* __restrict__ src, const int* __restrict__ dst) {
    int i = blockIdx.x * blockDim.x + threadIdx.x;
    if (i < EE) {
        bool m = (g_escore[i] >= g_thr[1]) && (g_nmask[src[i]] > 0.5f) && (g_nmask[dst[i]] > 0.5f);
        g_emask[i] = m ? 1.f : 0.f;
    }
}

// ================= CSR build =================
__global__ void zero_deg_kernel() {
    int i = blockIdx.x * blockDim.x + threadIdx.x;
    if (i < NN) g_deg[i] = 0;
}
__global__ void count_deg_kernel(const int* __restrict__ src) {
    int e = blockIdx.x * blockDim.x + threadIdx.x;
    if (e < EE) atomicAdd(&g_deg[src[e]], 1);
}
__global__ void scan_deg_kernel() {
    __shared__ int part[1024];
    const int CH = (NN + 1023) / 1024;
    int t = threadIdx.x;
    int s = 0;
    for (int j = 0; j < CH; j++) { int i = t * CH + j; if (i < NN) s += g_deg[i]; }
    part[t] = s;
    __syncthreads();
    if (t == 0) {
        int run = 0;
        for (int i = 0; i < 1024; i++) { int v = part[i]; part[i] = run; run += v; }
        g_off[NN] = run;
    }
    __syncthreads();
    int run = part[t];
    for (int j = 0; j < CH; j++) {
        int i = t * CH + j;
        if (i < NN) { g_off[i] = run; g_cur[i] = run; run += g_deg[i]; }
    }
}
__global__ void scatter_kernel(const int* __restrict__ src) {
    int e = blockIdx.x * blockDim.x + threadIdx.x;
    if (e < EE) {
        int p = atomicAdd(&g_cur[src[e]], 1);
        g_elist[p] = e;
    }
}

// ================= weight transpose + bf16 hi/lo split =================
__global__ void wconv_kernel(const float* __restrict__ W, __nv_bfloat16* __restrict__ hi,
                             __nv_bfloat16* __restrict__ lo, int K)
{
    int idx = blockIdx.x * blockDim.x + threadIdx.x;
    if (idx >= DE * K) return;
    int n = idx % DE, k = idx / DE;
    float x = W[(size_t)k * DE + n];
    __nv_bfloat16 h = __float2bfloat16(x);
    hi[(size_t)n * K + k] = h;
    lo[(size_t)n * K + k] = __float2bfloat16(x - __bfloat162float(h));
}

// ================= generic fp32 -> bf16 hi/lo split (same layout) =================
__global__ void split_kernel(const float* __restrict__ X, __nv_bfloat16* __restrict__ hi,
                             __nv_bfloat16* __restrict__ lo, size_t n4)
{
    size_t i = (size_t)blockIdx.x * blockDim.x + threadIdx.x;
    if (i >= n4) return;
    float4 x = reinterpret_cast<const float4*>(X)[i];
    __nv_bfloat162 h0 = __floats2bfloat162_rn(x.x, x.y);
    __nv_bfloat162 h1 = __floats2bfloat162_rn(x.z, x.w);
    uint2 hv, lv;
    hv.x = *reinterpret_cast<uint32_t*>(&h0);
    hv.y = *reinterpret_cast<uint32_t*>(&h1);
    lv.x = pack2bf(x.x - __bfloat162float(h0.x), x.y - __bfloat162float(h0.y));
    lv.y = pack2bf(x.z - __bfloat162float(h1.x), x.w - __bfloat162float(h1.y));
    reinterpret_cast<uint2*>(hi)[i] = hv;
    reinterpret_cast<uint2*>(lo)[i] = lv;
}

// ================= mma.sync bf16-split GEMM (A pre-split) =================
// C[M,512] = A[M,K] @ W^T + epi, 3-pass bf16 hi/lo split, A & B via cp.async.
// Tile 128x128, K-chunk 64, 3-stage ring (64KB/stage -> 192KB smem).
// AMODE: 0 direct rows, 1 gathered rows (gidx)
// EPI:   0 +bias, 1 mask*acc+bias, 2 acc+bias+mask*res -> split bf16 out, 3 gelu(acc+bias)
#define STAGE_BYTES 65536
#define GEMM_SMEM (3 * STAGE_BYTES)

template<int AMODE, int EPI>
__global__ __launch_bounds__(256, 1)
void mma_gemm(const __nv_bfloat16* __restrict__ Ahi, const __nv_bfloat16* __restrict__ Alo,
              const __nv_bfloat16* __restrict__ Bhi, const __nv_bfloat16* __restrict__ Blo,
              const float* __restrict__ bias, float* __restrict__ C,
              __nv_bfloat16* __restrict__ Chi, __nv_bfloat16* __restrict__ Clo,
              int M, int K,
              const float* __restrict__ rowmask, const int* __restrict__ gidx,
              const float* __restrict__ resA)
{
    extern __shared__ char sm[];
    const uint32_t sbase = (uint32_t)__cvta_generic_to_shared(sm);
    const int tid = threadIdx.x;
    const int w = tid >> 5, l = tid & 31;
    const int row0 = blockIdx.y * 128;
    const int n0 = blockIdx.x * 128;
    const int wm = w >> 2, wn = w & 3;

    float acc[4][4][4];
    #pragma unroll
    for (int i = 0; i < 4; i++)
        #pragma unroll
        for (int j = 0; j < 4; j++)
            #pragma unroll
            for (int p = 0; p < 4; p++) acc[i][j][p] = 0.f;

    // per-thread A source rows (4 rows: (tid>>3) + 32*i), clamped; gathered if AMODE==1
    int srow[4];
    #pragma unroll
    for (int i = 0; i < 4; i++) {
        int r = row0 + (tid >> 3) + 32 * i;
        if (r >= M) r = M - 1;
        srow[i] = (AMODE == 1) ? gidx[r] : r;
    }

    auto loadA = [&](int k0, int stage) {
        uint32_t sb = sbase + stage * STAGE_BYTES;
        #pragma unroll
        for (int i = 0; i < 4; i++) {
            int lin = tid + 256 * i;
            int r = lin >> 3, ch = lin & 7;
            uint32_t so = sb + r * 128 + (uint32_t)((ch ^ (r & 7)) * 16);
            size_t gi = (size_t)srow[i] * K + k0 + ch * 8;
            cpasync16(so, &Ahi[gi]);
            cpasync16(so + 16384, &Alo[gi]);
        }
    };
    auto loadB = [&](int k0, int stage) {
        uint32_t sb = sbase + stage * STAGE_BYTES + 32768;
        #pragma unroll
        for (int i = 0; i < 4; i++) {
            int lin = tid + 256 * i;
            int r = lin >> 3, ch = lin & 7;
            uint32_t so = sb + r * 128 + (uint32_t)((ch ^ (r & 7)) * 16);
            size_t gi = (size_t)(n0 + r) * K + k0 + ch * 8;
            cpasync16(so, &Bhi[gi]);
            cpasync16(so + 16384, &Blo[gi]);
        }
    };
    auto compute = [&](int stage) {
        uint32_t ab = sbase + stage * STAGE_BYTES;
        uint32_t bb = ab + 32768;
        #pragma unroll
        for (int ks = 0; ks < 4; ks++) {
            int kc = ks * 2;
            uint32_t ahi[4][4], alo[4][4];
            #pragma unroll
            for (int mf = 0; mf < 4; mf++) {
                int rr = wm * 64 + mf * 16 + (l & 15);
                int kch = kc + (l >> 4);
                uint32_t addr = ab + rr * 128 + (uint32_t)(((kch ^ (rr & 7))) * 16);
                ldm4(ahi[mf], addr);
                ldm4(alo[mf], addr + 16384);
            }
            uint32_t bhi[2][4], blo[2][4];
            #pragma unroll
            for (int ng = 0; ng < 2; ng++) {
                int nr = wn * 32 + ng * 16 + (l & 7) + ((l >> 4) << 3);
                int kch = kc + ((l >> 3) & 1);
                uint32_t addr = bb + nr * 128 + (uint32_t)(((kch ^ (nr & 7))) * 16);
                ldm4(bhi[ng], addr);
                ldm4(blo[ng], addr + 16384);
            }
            #pragma unroll
            for (int mf = 0; mf < 4; mf++) {
                #pragma unroll
                for (int nf = 0; nf < 4; nf++) {
                    int ng = nf >> 1, sb2 = (nf & 1) * 2;
                    mma_bf16(acc[mf][nf], ahi[mf], bhi[ng][sb2], bhi[ng][sb2 + 1]);
                    mma_bf16(acc[mf][nf], ahi[mf], blo[ng][sb2], blo[ng][sb2 + 1]);
                    mma_bf16(acc[mf][nf], alo[mf], bhi[ng][sb2], bhi[ng][sb2 + 1]);
                }
            }
        }
    };

    // ---- 3-stage pipeline ----
    const int nch = K >> 6;
    loadA(0, 0); loadB(0, 0); cp_commit();
    if (nch > 1) { loadA(64, 1); loadB(64, 1); cp_commit(); }
    else cp_commit();
    for (int c = 0; c < nch; c++) {
        __syncthreads();   // stage (c+2)%3 free (compute of chunk c-1 done everywhere)
        if (c + 2 < nch) { loadA((c + 2) * 64, (c + 2) % 3); loadB((c + 2) * 64, (c + 2) % 3); }
        cp_commit();       // always commit to keep group counting aligned
        CP_WAIT(2);        // chunk c's group complete
        __syncthreads();
        compute(c % 3);
    }

    // ---- epilogue ----
    #pragma unroll
    for (int mf = 0; mf < 4; mf++) {
        int gr0 = row0 + wm * 64 + mf * 16 + (l >> 2);
        #pragma unroll
        for (int nf = 0; nf < 4; nf++) {
            int gc = n0 + wn * 32 + nf * 8 + (l & 3) * 2;
            float b0 = bias[gc], b1 = bias[gc + 1];
            #pragma unroll
            for (int h = 0; h < 2; h++) {
                int grow = gr0 + 8 * h;
                if (grow >= M) continue;
                float a0 = acc[mf][nf][2 * h], a1 = acc[mf][nf][2 * h + 1];
                float v0, v1;
                if (EPI == 0) { v0 = a0 + b0; v1 = a1 + b1; }
                if (EPI == 1) {
                    float m = rowmask[grow];
                    v0 = m * a0 + b0; v1 = m * a1 + b1;
                }
                if (EPI == 2) {
                    float m = rowmask[grow];
                    v0 = a0 + b0 + m * resA[(size_t)grow * DE + gc];
                    v1 = a1 + b1 + m * resA[(size_t)grow * DE + gc + 1];
                }
                if (EPI == 3) {
                    v0 = a0 + b0; v1 = a1 + b1;
                    v0 = 0.5f * v0 * (1.0f + erff(v0 * 0.70710678118654752f));
                    v1 = 0.5f * v1 * (1.0f + erff(v1 * 0.70710678118654752f));
                }
                if (EPI == 2) {
                    // write split bf16 (feeds next GEMM); no fp32 write
                    __nv_bfloat162 hh = __floats2bfloat162_rn(v0, v1);
                    uint32_t hw = *reinterpret_cast<uint32_t*>(&hh);
                    uint32_t lw = pack2bf(v0 - __bfloat162float(hh.x), v1 - __bfloat162float(hh.y));
                    *reinterpret_cast<uint32_t*>(&Chi[(size_t)grow * DE + gc]) = hw;
                    *reinterpret_cast<uint32_t*>(&Clo[(size_t)grow * DE + gc]) = lw;
                } else {
                    *reinterpret_cast<float2*>(&C[(size_t)grow * DE + gc]) = make_float2(v0, v1);
                }
            }
        }
    }
}

// ================= attention logits: one warp per edge =================
__global__ void attn_scores_kernel(const int* __restrict__ src) {
    int warp = blockIdx.x * 8 + (threadIdx.x >> 5);
    int lane = threadIdx.x & 31;
    if (warp >= EE) return;
    int e = warp;
    const float4* qr = reinterpret_cast<const float4*>(g_q + (size_t)src[e] * DE);
    const float4* kr = reinterpret_cast<const float4*>(g_k + (size_t)e * DE);
    float s = 0.f;
    int base = lane * 4;
    #pragma unroll
    for (int j = 0; j < 4; j++) {
        float4 a = qr[base + j], b = kr[base + j];
        s += a.x * b.x + a.y * b.y + a.z * b.z + a.w * b.w;
    }
    s += __shfl_xor_sync(0xFFFFFFFFu, s, 1);
    s += __shfl_xor_sync(0xFFFFFFFFu, s, 2);
    if ((lane & 3) == 0) g_sc[(size_t)e * NH + (lane >> 2)] = s * 0.125f;
}

// ================= segment softmax + aggregation: one block per node =================
__global__ void softmax_agg_kernel() {
    int n = blockIdx.x;
    int off = g_off[n];
    int deg = g_off[n + 1] - off;
    __shared__ float m_sh[NH], d_sh[NH];
    __shared__ float attn_sh[64 * NH];
    int tid = threadIdx.x;
    int wid = tid >> 5, lane = tid & 31;
    {
        float mx = -INFINITY;
        for (int i = lane; i < deg; i += 32) {
            int e = g_elist[off + i];
            mx = fmaxf(mx, g_sc[(size_t)e * NH + wid]);
        }
        #pragma unroll
        for (int o = 16; o; o >>= 1) mx = fmaxf(mx, __shfl_xor_sync(0xFFFFFFFFu, mx, o));
        float sm = 0.f;
        for (int i = lane; i < deg; i += 32) {
            int e = g_elist[off + i];
            sm += expf(g_sc[(size_t)e * NH + wid] - mx);
        }
        #pragma unroll
        for (int o = 16; o; o >>= 1) sm += __shfl_xor_sync(0xFFFFFFFFu, sm, o);
        if (lane == 0) { m_sh[wid] = mx; d_sh[wid] = sm; }
    }
    __syncthreads();
    float2 acc = make_float2(0.f, 0.f);
    int d0 = tid * 2;
    int h = d0 >> 6;
    for (int base = 0; base < deg; base += 64) {
        int cnt = min(64, deg - base);
        __syncthreads();
        for (int idx = tid; idx < cnt * NH; idx += 256) {
            int j = idx >> 3, hh = idx & 7;
            int e = g_elist[off + base + j];
            attn_sh[idx] = expf(g_sc[(size_t)e * NH + hh] - m_sh[hh]) / d_sh[hh];
        }
        __syncthreads();
        for (int j = 0; j < cnt; j++) {
            int e = g_elist[off + base + j];
            float a = attn_sh[j * NH + h];
            float2 vv = *reinterpret_cast<const float2*>(g_v + (size_t)e * DE + d0);
            acc.x += a * vv.x;
            acc.y += a * vv.y;
        }
    }
    *reinterpret_cast<float2*>(g_agg + (size_t)n * DE + d0) = acc;
}

// ================= classifier: one warp per edge =================
__global__ void classify_kernel(const float* __restrict__ W2, const float* __restrict__ b2,
                                float* __restrict__ out) {
    __shared__ float W2s[DE * NC];
    int tid = threadIdx.x;
    for (int i = tid; i < DE * NC; i += 256) W2s[i] = W2[i];
    __syncthreads();
    int warp = blockIdx.x * 8 + (tid >> 5);
    if (warp >= EE) return;
    int lane = tid & 31;
    const float* hr = g_v + (size_t)warp * DE;
    float p[NC];
    #pragma unroll
    for (int c = 0; c < NC; c++) p[c] = 0.f;
    for (int k = lane; k < DE; k += 32) {
        float hv = hr[k];
        const float* wk = &W2s[k * NC];
        #pragma unroll
        for (int c = 0; c < NC; c++) p[c] += hv * wk[c];
    }
    #pragma unroll
    for (int c = 0; c < NC; c++) {
        #pragma unroll
        for (int o = 16; o; o >>= 1) p[c] += __shfl_xor_sync(0xFFFFFFFFu, p[c], o);
    }
    if (lane == 0) {
        #pragma unroll
        for (int c = 0; c < NC; c++) out[(size_t)warp * NC + c] = p[c] + b2[c];
    }
}

// ================= host launcher =================
extern "C" void kernel_launch(void* const* d_in, const int* in_sizes, int n_in,
                              void* d_out, int out_size)
{
    const float* node_features = (const float*)d_in[0];
    const float* edge_features = (const float*)d_in[1];
    const int*   edge_index    = (const int*)d_in[2];
    const float* nw = (const float*)d_in[4];
    const float* nb = (const float*)d_in[5];
    const float* ew = (const float*)d_in[6];
    const float* eb = (const float*)d_in[7];
    const float* Wq = (const float*)d_in[8];  const float* bq = (const float*)d_in[9];
    const float* Wk = (const float*)d_in[10]; const float* bk = (const float*)d_in[11];
    const float* Wv = (const float*)d_in[12]; const float* bv = (const float*)d_in[13];
    const float* Wo = (const float*)d_in[14]; const float* bo = (const float*)d_in[15];
    const float* W1 = (const float*)d_in[16]; const float* b1 = (const float*)d_in[17];
    const float* W2 = (const float*)d_in[18]; const float* b2 = (const float*)d_in[19];
    float* out = (float*)d_out;
    const int* src = edge_index;
    const int* dst = edge_index + EE;

    float *qp, *kp, *vp, *aggp, *nsp, *esp, *emp;
    __nv_bfloat16 *whi, *wlo, *efhi, *eflo, *nfhi, *nflo, *aghi, *aglo;
    cudaGetSymbolAddress((void**)&qp,   g_q);
    cudaGetSymbolAddress((void**)&kp,   g_k);
    cudaGetSymbolAddress((void**)&vp,   g_v);
    cudaGetSymbolAddress((void**)&aggp, g_agg);
    cudaGetSymbolAddress((void**)&nsp,  g_nscore);
    cudaGetSymbolAddress((void**)&esp,  g_escore);
    cudaGetSymbolAddress((void**)&emp,  g_emask);
    cudaGetSymbolAddress((void**)&whi,  g_whi);
    cudaGetSymbolAddress((void**)&wlo,  g_wlo);
    cudaGetSymbolAddress((void**)&efhi, g_efhi);
    cudaGetSymbolAddress((void**)&eflo, g_eflo);
    cudaGetSymbolAddress((void**)&nfhi, g_nfhi);
    cudaGetSymbolAddress((void**)&nflo, g_nflo);
    cudaGetSymbolAddress((void**)&aghi, g_agghi);
    cudaGetSymbolAddress((void**)&aglo, g_agglo);

    cudaFuncSetAttribute((const void*)mma_gemm<0,0>, cudaFuncAttributeMaxDynamicSharedMemorySize, GEMM_SMEM);
    cudaFuncSetAttribute((const void*)mma_gemm<0,1>, cudaFuncAttributeMaxDynamicSharedMemorySize, GEMM_SMEM);
    cudaFuncSetAttribute((const void*)mma_gemm<1,2>, cudaFuncAttributeMaxDynamicSharedMemorySize, GEMM_SMEM);
    cudaFuncSetAttribute((const void*)mma_gemm<0,3>, cudaFuncAttributeMaxDynamicSharedMemorySize, GEMM_SMEM);

    // 0a. weight transpose + split (slots: 0=Wq K=256, 1=Wk, 2=Wv, 3=Wo, 4=W1)
    wconv_kernel<<<(DE * DN + 255) / 256, 256>>>(Wq, whi + 0 * (size_t)DE * DE, wlo + 0 * (size_t)DE * DE, DN);
    wconv_kernel<<<(DE * DE + 255) / 256, 256>>>(Wk, whi + 1 * (size_t)DE * DE, wlo + 1 * (size_t)DE * DE, DE);
    wconv_kernel<<<(DE * DE + 255) / 256, 256>>>(Wv, whi + 2 * (size_t)DE * DE, wlo + 2 * (size_t)DE * DE, DE);
    wconv_kernel<<<(DE * DE + 255) / 256, 256>>>(Wo, whi + 3 * (size_t)DE * DE, wlo + 3 * (size_t)DE * DE, DE);
    wconv_kernel<<<(DE * DE + 255) / 256, 256>>>(W1, whi + 4 * (size_t)DE * DE, wlo + 4 * (size_t)DE * DE, DE);
    // 0b. activation splits (unmasked; mask applied in GEMM epilogue)
    split_kernel<<<((size_t)EE * DE / 4 + 255) / 256, 256>>>(edge_features, efhi, eflo, (size_t)EE * DE / 4);
    split_kernel<<<((size_t)NN * DN / 4 + 255) / 256, 256>>>(node_features, nfhi, nflo, (size_t)NN * DN / 4);

    // 1. linear scorers (exact fp32 -> masks stay bit-exact)
    score_kernel<<<(NN + 7) / 8, 256>>>(node_features, nw, nb, nsp, NN, DN);
    score_kernel<<<(EE + 7) / 8, 256>>>(edge_features, ew, eb, esp, EE, DE);

    // 2. exact top-k thresholds
    rs_init<<<1, 256>>>(KN);
    for (int shift = 24; shift >= 0; shift -= 8) {
        rs_hist<<<64, 256>>>(nsp, NN, shift);
        rs_select<<<1, 256>>>(shift, 0);
    }
    rs_init<<<1, 256>>>(KE);
    for (int shift = 24; shift >= 0; shift -= 8) {
        rs_hist<<<256, 256>>>(esp, EE, shift);
        rs_select<<<1, 256>>>(shift, 1);
    }

    // 3. masks
    node_mask_kernel<<<(NN + 255) / 256, 256>>>();
    edge_mask_kernel<<<(EE + 255) / 256, 256>>>(src, dst);

    // 4. CSR by source node
    zero_deg_kernel<<<(NN + 255) / 256, 256>>>();
    count_deg_kernel<<<(EE + 255) / 256, 256>>>(src);
    scan_deg_kernel<<<1, 1024>>>();
    scatter_kernel<<<(EE + 255) / 256, 256>>>(src);

    // 5. projections (pure tensor-pipe mainloops)
    dim3 gq(4, (NN + 127) / 128);
    mma_gemm<0,0><<<gq, 256, GEMM_SMEM>>>(nfhi, nflo, whi + 0 * (size_t)DE * DE, wlo + 0 * (size_t)DE * DE,
                                          bq, qp, nullptr, nullptr, NN, DN, nullptr, nullptr, nullptr);
    dim3 ge(4, EE / 128);
    mma_gemm<0,1><<<ge, 256, GEMM_SMEM>>>(efhi, eflo, whi + 1 * (size_t)DE * DE, wlo + 1 * (size_t)DE * DE,
                                          bk, kp, nullptr, nullptr, EE, DE, emp, nullptr, nullptr);
    mma_gemm<0,1><<<ge, 256, GEMM_SMEM>>>(efhi, eflo, whi + 2 * (size_t)DE * DE, wlo + 2 * (size_t)DE * DE,
                                          bv, vp, nullptr, nullptr, EE, DE, emp, nullptr, nullptr);

    // 6. attention logits, segment softmax + aggregation
    attn_scores_kernel<<<EE / 8, 256>>>(src);
    softmax_agg_kernel<<<NN, 256>>>();

    // 6b. split agg for o-proj A
    split_kernel<<<((size_t)NN * DE / 4 + 255) / 256, 256>>>(aggp, aghi, aglo, (size_t)NN * DE / 4);

    // 7. o-proj + residual, gathered rows; writes hidden as bf16 hi/lo (reuses ef split buffers)
    mma_gemm<1,2><<<ge, 256, GEMM_SMEM>>>(aghi, aglo, whi + 3 * (size_t)DE * DE, wlo + 3 * (size_t)DE * DE,
                                          bo, nullptr, efhi, eflo, EE, DE, emp, src, edge_features);

    // 8. MLP hidden + exact GELU -> g_v becomes h
    mma_gemm<0,3><<<ge, 256, GEMM_SMEM>>>(efhi, eflo, whi + 4 * (size_t)DE * DE, wlo + 4 * (size_t)DE * DE,
                                          b1, vp, nullptr, nullptr, EE, DE, nullptr, nullptr, nullptr);

    // 9. classifier head
    classify_kernel<<<EE / 8, 256>>>(W2, b2, out);
}

// round 7
// speedup vs baseline: 10.4073x; 4.5479x over previous
#include <cuda_runtime.h>
#include <cuda_bf16.h>
#include <math.h>
#include <stdint.h>

// ---------------- problem constants ----------------
#define NN 10000
#define EE 160000
#define DN 256
#define DE 512
#define NH 8
#define NC 10
#define KN 5000
#define KE 80000
#define MAXL 80000   // worst-case live edges (edge top-k keeps exactly KE)

// ---------------- device scratch ----------------
__device__ float g_q[(size_t)NN * DE];            // node queries
__device__ float g_kc[(size_t)MAXL * DE];         // compact live keys
__device__ float g_vc[(size_t)MAXL * DE];         // compact live values
__device__ float g_efw1[(size_t)MAXL * DE];       // compact live ef@W1
__device__ float g_scc[(size_t)MAXL * NH];        // compact live attention logits
__device__ float g_qbk[(size_t)NN * NH];          // q[n]·bk per head (dead-edge logit)
__device__ float g_agg[(size_t)NN * DE];          // per-node aggregate
__device__ float g_nt[(size_t)NN * DE];           // nodeterm = (agg@Wo+bo)@W1+b1
__device__ float g_outc[(size_t)NN * NC];         // per-node classifier (dead edges)
__device__ float g_nscore[NN];
__device__ float g_escore[EE];
__device__ unsigned char g_emask8[EE];
__device__ float g_thr[2];
__device__ float g_zb[DE];                        // zero bias
// bf16 hi/lo splits
__device__ __nv_bfloat16 g_cefhi[(size_t)MAXL * DE];
__device__ __nv_bfloat16 g_ceflo[(size_t)MAXL * DE];
__device__ __nv_bfloat16 g_nfhi[(size_t)NN * DN];
__device__ __nv_bfloat16 g_nflo[(size_t)NN * DN];
__device__ __nv_bfloat16 g_agghi[(size_t)NN * DE];
__device__ __nv_bfloat16 g_agglo[(size_t)NN * DE];
__device__ __nv_bfloat16 g_awhi[(size_t)NN * DE];
__device__ __nv_bfloat16 g_awlo[(size_t)NN * DE];
// weights: slot 0=Wq(K=256),1=Wk,2=Wv,3=Wo,4=W1  ([Nout=512, K] K-major)
__device__ __nv_bfloat16 g_whi[5][DE * DE];
__device__ __nv_bfloat16 g_wlo[5][DE * DE];
// compaction / CSR
__device__ int g_live[MAXL];
__device__ int g_blkcnt[625];
__device__ int g_blkoff[625];
__device__ int g_nlive;
__device__ int g_degt[NN];
__device__ int g_degl[NN];
__device__ int g_off[NN + 1];
__device__ int g_cur[NN];
__device__ int g_elist[MAXL];

// ================= PTX helpers =================
__device__ __forceinline__ void ldm4(uint32_t* r, uint32_t a) {
    asm volatile("ldmatrix.sync.aligned.m8n8.x4.shared.b16 {%0,%1,%2,%3}, [%4];"
                 : "=r"(r[0]), "=r"(r[1]), "=r"(r[2]), "=r"(r[3]) : "r"(a));
}
__device__ __forceinline__ void mma_bf16(float* d, const uint32_t* a, uint32_t b0, uint32_t b1) {
    asm volatile("mma.sync.aligned.m16n8k16.row.col.f32.bf16.bf16.f32 "
                 "{%0,%1,%2,%3},{%4,%5,%6,%7},{%8,%9},{%0,%1,%2,%3};"
                 : "+f"(d[0]), "+f"(d[1]), "+f"(d[2]), "+f"(d[3])
                 : "r"(a[0]), "r"(a[1]), "r"(a[2]), "r"(a[3]), "r"(b0), "r"(b1));
}
__device__ __forceinline__ void cpasync16(uint32_t s, const void* g) {
    asm volatile("cp.async.cg.shared.global [%0], [%1], 16;" :: "r"(s), "l"(g));
}
__device__ __forceinline__ void cp_commit() { asm volatile("cp.async.commit_group;" ::: "memory"); }
#define CP_WAIT(n) asm volatile("cp.async.wait_group %0;" :: "n"(n) : "memory")

__device__ __forceinline__ uint32_t pack2bf(float x, float y) {
    __nv_bfloat162 h = __floats2bfloat162_rn(x, y);
    return *reinterpret_cast<uint32_t*>(&h);
}
__device__ __forceinline__ float gelu_exact(float x) {
    return 0.5f * x * (1.0f + erff(x * 0.70710678118654752f));
}

// ================= scorers: one warp per row =================
__global__ void score_kernel(const float* __restrict__ X, const float* __restrict__ w,
                             const float* __restrict__ b, float* __restrict__ out,
                             int M, int K)
{
    int warp = (blockIdx.x * blockDim.x + threadIdx.x) >> 5;
    int lane = threadIdx.x & 31;
    if (warp >= M) return;
    const float* row = X + (size_t)warp * K;
    float s = 0.f;
    for (int k = lane; k < K; k += 32) s += row[k] * w[k];
    #pragma unroll
    for (int o = 16; o; o >>= 1) s += __shfl_xor_sync(0xFFFFFFFFu, s, o);
    if (lane == 0) out[warp] = s + b[0];
}

// ================= zero init =================
__global__ void zero_kernel() {
    int i = blockIdx.x * blockDim.x + threadIdx.x;
    if (i < NN) { g_degt[i] = 0; g_degl[i] = 0; }
    if (i < DE) g_zb[i] = 0.f;
}

// ================= single-kernel dual top-k (exact, 4x8-bit radix) =================
__device__ __forceinline__ unsigned f2u_ord(float x) {
    unsigned u = __float_as_uint(x);
    return (u & 0x80000000u) ? ~u : (u | 0x80000000u);
}
__global__ void topk_kernel() {
    int b = blockIdx.x;                       // 0: nodes, 1: edges
    const float* data = b ? g_escore : g_nscore;
    int n = b ? EE : NN;
    unsigned k = b ? KE : KN;
    __shared__ unsigned hist[256];
    __shared__ unsigned prefix_s, krem_s;
    int tid = threadIdx.x;
    if (tid == 0) { prefix_s = 0u; krem_s = k; }
    __syncthreads();
    for (int shift = 24; shift >= 0; shift -= 8) {
        if (tid < 256) hist[tid] = 0u;
        __syncthreads();
        unsigned prefix = prefix_s;
        unsigned maskhi = (shift == 24) ? 0u : (0xFFFFFFFFu << (shift + 8));
        for (int i = tid; i < n; i += blockDim.x) {
            unsigned u = f2u_ord(data[i]);
            if ((u & maskhi) == prefix) atomicAdd(&hist[(u >> shift) & 255], 1u);
        }
        __syncthreads();
        if (tid == 0) {
            unsigned krem = krem_s, cum = 0; int digit = 0;
            for (int d = 255; d >= 0; d--) {
                unsigned c = hist[d];
                if (cum + c >= krem) { digit = d; break; }
                cum += c;
            }
            prefix_s |= ((unsigned)digit) << shift;
            krem_s = krem - cum;
        }
        __syncthreads();
    }
    if (tid == 0) {
        unsigned u = prefix_s;
        u = (u & 0x80000000u) ? (u & 0x7FFFFFFFu) : ~u;
        g_thr[b] = __uint_as_float(u);
    }
}

// ================= edge mask + degree counts + per-block live counts =================
__global__ void emask_count_kernel(const int* __restrict__ src, const int* __restrict__ dst) {
    int e = blockIdx.x * 256 + threadIdx.x;
    bool live = false;
    if (e < EE) {
        float tn = g_thr[0], te = g_thr[1];
        live = (g_escore[e] >= te) && (g_nscore[src[e]] >= tn) && (g_nscore[dst[e]] >= tn);
        g_emask8[e] = live ? 1 : 0;
        atomicAdd(&g_degt[src[e]], 1);
        if (live) atomicAdd(&g_degl[src[e]], 1);
    }
    int cnt = __syncthreads_count(live);
    if (threadIdx.x == 0) g_blkcnt[blockIdx.x] = cnt;
}

// ================= scans: compaction offsets + live CSR offsets =================
__global__ void scan2_kernel() {   // 1 block, 1024 threads
    int t = threadIdx.x;
    if (t == 0) {
        int run = 0;
        for (int i = 0; i < 625; i++) { g_blkoff[i] = run; run += g_blkcnt[i]; }
        g_nlive = run > MAXL ? MAXL : run;
    }
    __syncthreads();
    __shared__ int part[1024];
    const int CH = (NN + 1023) / 1024;
    int s = 0;
    for (int j = 0; j < CH; j++) { int i = t * CH + j; if (i < NN) s += g_degl[i]; }
    part[t] = s;
    __syncthreads();
    if (t == 0) {
        int run = 0;
        for (int i = 0; i < 1024; i++) { int v = part[i]; part[i] = run; run += v; }
        g_off[NN] = run;
    }
    __syncthreads();
    int run = part[t];
    for (int j = 0; j < CH; j++) {
        int i = t * CH + j;
        if (i < NN) { g_off[i] = run; g_cur[i] = run; run += g_degl[i]; }
    }
}

// ================= deterministic compaction (order-preserving) =================
__global__ void compact_kernel() {
    int e = blockIdx.x * 256 + threadIdx.x;
    bool m = (e < EE) && g_emask8[e];
    int wid = threadIdx.x >> 5, lane = threadIdx.x & 31;
    unsigned bal = __ballot_sync(0xFFFFFFFFu, m);
    __shared__ int wcnt[8];
    if (lane == 0) wcnt[wid] = __popc(bal);
    __syncthreads();
    int woff = 0;
    for (int i = 0; i < wid; i++) woff += wcnt[i];
    if (m) {
        int pos = g_blkoff[blockIdx.x] + woff + __popc(bal & ((1u << lane) - 1));
        if (pos < MAXL) g_live[pos] = e;
    }
}

// ================= CSR scatter of compact indices by src node =================
__global__ void csr_scatter_kernel(const int* __restrict__ src) {
    int c = blockIdx.x * 256 + threadIdx.x;
    if (c < g_nlive) {
        int e = g_live[c];
        int p = atomicAdd(&g_cur[src[e]], 1);
        g_elist[p] = c;
    }
}

// ================= gather + split live ef rows =================
__global__ void gather_split_kernel(const float* __restrict__ ef) {
    int nl = g_nlive;
    size_t total = (size_t)nl * 128;
    size_t stride = (size_t)gridDim.x * blockDim.x;
    for (size_t id = (size_t)blockIdx.x * blockDim.x + threadIdx.x; id < total; id += stride) {
        int c = (int)(id >> 7), j = (int)(id & 127);
        int e = g_live[c];
        float4 x = reinterpret_cast<const float4*>(ef)[(size_t)e * 128 + j];
        __nv_bfloat162 h0 = __floats2bfloat162_rn(x.x, x.y);
        __nv_bfloat162 h1 = __floats2bfloat162_rn(x.z, x.w);
        uint2 hv, lv;
        hv.x = *reinterpret_cast<uint32_t*>(&h0);
        hv.y = *reinterpret_cast<uint32_t*>(&h1);
        lv.x = pack2bf(x.x - __bfloat162float(h0.x), x.y - __bfloat162float(h0.y));
        lv.y = pack2bf(x.z - __bfloat162float(h1.x), x.w - __bfloat162float(h1.y));
        reinterpret_cast<uint2*>(g_cefhi)[(size_t)c * 128 + j] = hv;
        reinterpret_cast<uint2*>(g_ceflo)[(size_t)c * 128 + j] = lv;
    }
}

// ================= generic fp32 -> bf16 hi/lo split =================
__global__ void split_kernel(const float* __restrict__ X, __nv_bfloat16* __restrict__ hi,
                             __nv_bfloat16* __restrict__ lo, size_t n4)
{
    size_t i = (size_t)blockIdx.x * blockDim.x + threadIdx.x;
    if (i >= n4) return;
    float4 x = reinterpret_cast<const float4*>(X)[i];
    __nv_bfloat162 h0 = __floats2bfloat162_rn(x.x, x.y);
    __nv_bfloat162 h1 = __floats2bfloat162_rn(x.z, x.w);
    uint2 hv, lv;
    hv.x = *reinterpret_cast<uint32_t*>(&h0);
    hv.y = *reinterpret_cast<uint32_t*>(&h1);
    lv.x = pack2bf(x.x - __bfloat162float(h0.x), x.y - __bfloat162float(h0.y));
    lv.y = pack2bf(x.z - __bfloat162float(h1.x), x.w - __bfloat162float(h1.y));
    reinterpret_cast<uint2*>(hi)[i] = hv;
    reinterpret_cast<uint2*>(lo)[i] = lv;
}

// ================= all 5 weight transposes + splits in one kernel =================
__global__ void wconv_all(const float* __restrict__ Wq, const float* __restrict__ Wk,
                          const float* __restrict__ Wv, const float* __restrict__ Wo,
                          const float* __restrict__ W1)
{
    int idx = blockIdx.x * 256 + threadIdx.x;
    const int S0 = DE * DN;     // 131072
    const int SB = DE * DE;     // 262144
    int slot, K, r;
    const float* W;
    if (idx < S0) { slot = 0; K = DN; r = idx; W = Wq; }
    else {
        int t = idx - S0;
        slot = 1 + t / SB;
        if (slot > 4) return;
        r = t % SB; K = DE;
        W = (slot == 1) ? Wk : (slot == 2) ? Wv : (slot == 3) ? Wo : W1;
    }
    int n = r % DE, k = r / DE;
    float x = W[(size_t)k * DE + n];
    __nv_bfloat16 h = __float2bfloat16(x);
    g_whi[slot][n * K + k] = h;
    g_wlo[slot][n * K + k] = __float2bfloat16(x - __bfloat162float(h));
}

// ================= mma.sync bf16-split GEMM (pre-split A & B) =================
// C[M,512] = A[M,K] @ W^T + bias ; EPI 0: fp32 C ; EPI 4: split bf16 Chi/Clo
#define STAGE_BYTES 65536
#define GEMM_SMEM (3 * STAGE_BYTES)

template<int EPI>
__global__ __launch_bounds__(256, 1)
void mma_gemm(const __nv_bfloat16* __restrict__ Ahi, const __nv_bfloat16* __restrict__ Alo,
              const __nv_bfloat16* __restrict__ Bhi, const __nv_bfloat16* __restrict__ Blo,
              const float* __restrict__ bias, float* __restrict__ C,
              __nv_bfloat16* __restrict__ Chi, __nv_bfloat16* __restrict__ Clo,
              int Mstat, int K, const int* __restrict__ Mdyn)
{
    const int M = Mdyn ? *Mdyn : Mstat;
    const int row0 = blockIdx.y * 128;
    if (row0 >= M) return;
    extern __shared__ char sm[];
    const uint32_t sbase = (uint32_t)__cvta_generic_to_shared(sm);
    const int tid = threadIdx.x;
    const int w = tid >> 5, l = tid & 31;
    const int n0 = blockIdx.x * 128;
    const int wm = w >> 2, wn = w & 3;

    float acc[4][4][4];
    #pragma unroll
    for (int i = 0; i < 4; i++)
        #pragma unroll
        for (int j = 0; j < 4; j++)
            #pragma unroll
            for (int p = 0; p < 4; p++) acc[i][j][p] = 0.f;

    int srow[4];
    #pragma unroll
    for (int i = 0; i < 4; i++) {
        int r = row0 + (tid >> 3) + 32 * i;
        srow[i] = (r >= M) ? (M - 1) : r;
    }

    auto loadA = [&](int k0, int stage) {
        uint32_t sb = sbase + stage * STAGE_BYTES;
        #pragma unroll
        for (int i = 0; i < 4; i++) {
            int lin = tid + 256 * i;
            int r = lin >> 3, ch = lin & 7;
            uint32_t so = sb + r * 128 + (uint32_t)((ch ^ (r & 7)) * 16);
            size_t gi = (size_t)srow[i] * K + k0 + ch * 8;
            cpasync16(so, &Ahi[gi]);
            cpasync16(so + 16384, &Alo[gi]);
        }
    };
    auto loadB = [&](int k0, int stage) {
        uint32_t sb = sbase + stage * STAGE_BYTES + 32768;
        #pragma unroll
        for (int i = 0; i < 4; i++) {
            int lin = tid + 256 * i;
            int r = lin >> 3, ch = lin & 7;
            uint32_t so = sb + r * 128 + (uint32_t)((ch ^ (r & 7)) * 16);
            size_t gi = (size_t)(n0 + r) * K + k0 + ch * 8;
            cpasync16(so, &Bhi[gi]);
            cpasync16(so + 16384, &Blo[gi]);
        }
    };
    auto compute = [&](int stage) {
        uint32_t ab = sbase + stage * STAGE_BYTES;
        uint32_t bb = ab + 32768;
        #pragma unroll
        for (int ks = 0; ks < 4; ks++) {
            int kc = ks * 2;
            uint32_t ahi[4][4], alo[4][4];
            #pragma unroll
            for (int mf = 0; mf < 4; mf++) {
                int rr = wm * 64 + mf * 16 + (l & 15);
                int kch = kc + (l >> 4);
                uint32_t addr = ab + rr * 128 + (uint32_t)(((kch ^ (rr & 7))) * 16);
                ldm4(ahi[mf], addr);
                ldm4(alo[mf], addr + 16384);
            }
            uint32_t bhi[2][4], blo[2][4];
            #pragma unroll
            for (int ng = 0; ng < 2; ng++) {
                int nr = wn * 32 + ng * 16 + (l & 7) + ((l >> 4) << 3);
                int kch = kc + ((l >> 3) & 1);
                uint32_t addr = bb + nr * 128 + (uint32_t)(((kch ^ (nr & 7))) * 16);
                ldm4(bhi[ng], addr);
                ldm4(blo[ng], addr + 16384);
            }
            #pragma unroll
            for (int mf = 0; mf < 4; mf++) {
                #pragma unroll
                for (int nf = 0; nf < 4; nf++) {
                    int ng = nf >> 1, sb2 = (nf & 1) * 2;
                    mma_bf16(acc[mf][nf], ahi[mf], bhi[ng][sb2], bhi[ng][sb2 + 1]);
                    mma_bf16(acc[mf][nf], ahi[mf], blo[ng][sb2], blo[ng][sb2 + 1]);
                    mma_bf16(acc[mf][nf], alo[mf], bhi[ng][sb2], bhi[ng][sb2 + 1]);
                }
            }
        }
    };

    const int nch = K >> 6;
    loadA(0, 0); loadB(0, 0); cp_commit();
    if (nch > 1) { loadA(64, 1); loadB(64, 1); cp_commit(); }
    else cp_commit();
    for (int c = 0; c < nch; c++) {
        __syncthreads();
        if (c + 2 < nch) { loadA((c + 2) * 64, (c + 2) % 3); loadB((c + 2) * 64, (c + 2) % 3); }
        cp_commit();
        CP_WAIT(2);
        __syncthreads();
        compute(c % 3);
    }

    #pragma unroll
    for (int mf = 0; mf < 4; mf++) {
        int gr0 = row0 + wm * 64 + mf * 16 + (l >> 2);
        #pragma unroll
        for (int nf = 0; nf < 4; nf++) {
            int gc = n0 + wn * 32 + nf * 8 + (l & 3) * 2;
            float b0 = bias[gc], b1 = bias[gc + 1];
            #pragma unroll
            for (int h = 0; h < 2; h++) {
                int grow = gr0 + 8 * h;
                if (grow >= M) continue;
                float v0 = acc[mf][nf][2 * h] + b0;
                float v1 = acc[mf][nf][2 * h + 1] + b1;
                if (EPI == 4) {
                    __nv_bfloat162 hh = __floats2bfloat162_rn(v0, v1);
                    uint32_t hw = *reinterpret_cast<uint32_t*>(&hh);
                    uint32_t lw = pack2bf(v0 - __bfloat162float(hh.x), v1 - __bfloat162float(hh.y));
                    *reinterpret_cast<uint32_t*>(&Chi[(size_t)grow * DE + gc]) = hw;
                    *reinterpret_cast<uint32_t*>(&Clo[(size_t)grow * DE + gc]) = lw;
                } else {
                    *reinterpret_cast<float2*>(&C[(size_t)grow * DE + gc]) = make_float2(v0, v1);
                }
            }
        }
    }
}

// ================= qbk: dead-edge logit per node/head =================
__global__ void qbk_kernel(const float* __restrict__ bk) {
    int n = blockIdx.x * 8 + (threadIdx.x >> 5);
    int lane = threadIdx.x & 31;
    if (n >= NN) return;
    const float4* qr = reinterpret_cast<const float4*>(g_q + (size_t)n * DE);
    const float4* br = reinterpret_cast<const float4*>(bk);
    float s = 0.f;
    int base = lane * 4;
    #pragma unroll
    for (int j = 0; j < 4; j++) {
        float4 a = qr[base + j], b = br[base + j];
        s += a.x * b.x + a.y * b.y + a.z * b.z + a.w * b.w;
    }
    s += __shfl_xor_sync(0xFFFFFFFFu, s, 1);
    s += __shfl_xor_sync(0xFFFFFFFFu, s, 2);
    if ((lane & 3) == 0) g_qbk[(size_t)n * NH + (lane >> 2)] = s * 0.125f;
}

// ================= attention logits: one warp per live edge =================
__global__ void attn_live_kernel(const int* __restrict__ src) {
    int c = blockIdx.x * 8 + (threadIdx.x >> 5);
    int lane = threadIdx.x & 31;
    if (c >= g_nlive) return;
    int e = g_live[c];
    const float4* qr = reinterpret_cast<const float4*>(g_q + (size_t)src[e] * DE);
    const float4* kr = reinterpret_cast<const float4*>(g_kc + (size_t)c * DE);
    float s = 0.f;
    int base = lane * 4;
    #pragma unroll
    for (int j = 0; j < 4; j++) {
        float4 a = qr[base + j], b = kr[base + j];
        s += a.x * b.x + a.y * b.y + a.z * b.z + a.w * b.w;
    }
    s += __shfl_xor_sync(0xFFFFFFFFu, s, 1);
    s += __shfl_xor_sync(0xFFFFFFFFu, s, 2);
    if ((lane & 3) == 0) g_scc[(size_t)c * NH + (lane >> 2)] = s * 0.125f;
}

// ================= segment softmax + aggregation (live + analytic dead) =================
__global__ void softmax_agg_kernel(const float* __restrict__ bv) {
    int n = blockIdx.x;
    int off = g_off[n];
    int degl = g_off[n + 1] - off;
    int ndead = g_degt[n] - degl;
    int tid = threadIdx.x;
    int wid = tid >> 5, lane = tid & 31;
    int d0 = tid * 2;

    if (degl + ndead == 0) {
        *reinterpret_cast<float2*>(g_agg + (size_t)n * DE + d0) = make_float2(0.f, 0.f);
        return;
    }
    __shared__ float m_sh[NH], d_sh[NH], cdead_sh[NH];
    __shared__ float attn_sh[64 * NH];
    {
        float qb = g_qbk[(size_t)n * NH + wid];
        float mx = -INFINITY;
        for (int i = lane; i < degl; i += 32) {
            int c = g_elist[off + i];
            mx = fmaxf(mx, g_scc[(size_t)c * NH + wid]);
        }
        #pragma unroll
        for (int o = 16; o; o >>= 1) mx = fmaxf(mx, __shfl_xor_sync(0xFFFFFFFFu, mx, o));
        if (ndead > 0) mx = fmaxf(mx, qb);
        float sm = 0.f;
        for (int i = lane; i < degl; i += 32) {
            int c = g_elist[off + i];
            sm += expf(g_scc[(size_t)c * NH + wid] - mx);
        }
        #pragma unroll
        for (int o = 16; o; o >>= 1) sm += __shfl_xor_sync(0xFFFFFFFFu, sm, o);
        if (lane == 0) {
            float dterm = (ndead > 0) ? (float)ndead * expf(qb - mx) : 0.f;
            float den = sm + dterm;
            m_sh[wid] = mx; d_sh[wid] = den; cdead_sh[wid] = dterm / den;
        }
    }
    __syncthreads();
    float2 acc = make_float2(0.f, 0.f);
    int h = d0 >> 6;
    for (int base = 0; base < degl; base += 64) {
        int cnt = min(64, degl - base);
        __syncthreads();
        for (int idx = tid; idx < cnt * NH; idx += 256) {
            int j = idx >> 3, hh = idx & 7;
            int c = g_elist[off + base + j];
            attn_sh[idx] = expf(g_scc[(size_t)c * NH + hh] - m_sh[hh]) / d_sh[hh];
        }
        __syncthreads();
        for (int j = 0; j < cnt; j++) {
            int c = g_elist[off + base + j];
            float a = attn_sh[j * NH + h];
            float2 vv = *reinterpret_cast<const float2*>(g_vc + (size_t)c * DE + d0);
            acc.x += a * vv.x;
            acc.y += a * vv.y;
        }
    }
    float cd = cdead_sh[h];
    acc.x += cd * bv[d0];
    acc.y += cd * bv[d0 + 1];
    *reinterpret_cast<float2*>(g_agg + (size_t)n * DE + d0) = acc;
}

// ================= per-node classifier (dead-edge output) =================
__global__ void classify_node_kernel(const float* __restrict__ W2, const float* __restrict__ b2) {
    __shared__ float W2s[DE * NC];
    int tid = threadIdx.x;
    for (int i = tid; i < DE * NC; i += 256) W2s[i] = W2[i];
    __syncthreads();
    int n = blockIdx.x * 8 + (tid >> 5);
    if (n >= NN) return;
    int lane = tid & 31;
    const float* ntr = g_nt + (size_t)n * DE;
    float p[NC];
    #pragma unroll
    for (int c = 0; c < NC; c++) p[c] = 0.f;
    for (int k = lane; k < DE; k += 32) {
        float hv = gelu_exact(ntr[k]);
        const float* wk = &W2s[k * NC];
        #pragma unroll
        for (int c = 0; c < NC; c++) p[c] += hv * wk[c];
    }
    #pragma unroll
    for (int c = 0; c < NC; c++) {
        #pragma unroll
        for (int o = 16; o; o >>= 1) p[c] += __shfl_xor_sync(0xFFFFFFFFu, p[c], o);
    }
    if (lane == 0) {
        #pragma unroll
        for (int c = 0; c < NC; c++) g_outc[(size_t)n * NC + c] = p[c] + b2[c];
    }
}

// ================= live-edge output: gelu(nt[src]+efW1) @ W2 =================
__global__ void live_out_kernel(const int* __restrict__ src, const float* __restrict__ W2,
                                const float* __restrict__ b2, float* __restrict__ out) {
    __shared__ float W2s[DE * NC];
    int tid = threadIdx.x;
    for (int i = tid; i < DE * NC; i += 256) W2s[i] = W2[i];
    __syncthreads();
    int c = blockIdx.x * 8 + (tid >> 5);
    if (c >= g_nlive) return;
    int e = g_live[c];
    int lane = tid & 31;
    const float* ntr = g_nt + (size_t)src[e] * DE;
    const float* fr = g_efw1 + (size_t)c * DE;
    float p[NC];
    #pragma unroll
    for (int cc = 0; cc < NC; cc++) p[cc] = 0.f;
    for (int k = lane; k < DE; k += 32) {
        float hv = gelu_exact(ntr[k] + fr[k]);
        const float* wk = &W2s[k * NC];
        #pragma unroll
        for (int cc = 0; cc < NC; cc++) p[cc] += hv * wk[cc];
    }
    #pragma unroll
    for (int cc = 0; cc < NC; cc++) {
        #pragma unroll
        for (int o = 16; o; o >>= 1) p[cc] += __shfl_xor_sync(0xFFFFFFFFu, p[cc], o);
    }
    if (lane == 0) {
        #pragma unroll
        for (int cc = 0; cc < NC; cc++) out[(size_t)e * NC + cc] = p[cc] + b2[cc];
    }
}

// ================= dead-edge output: copy per-node classifier =================
__global__ void dead_out_kernel(const int* __restrict__ src, float* __restrict__ out) {
    int e = blockIdx.x * 256 + threadIdx.x;
    if (e >= EE || g_emask8[e]) return;
    const float* s = g_outc + (size_t)src[e] * NC;
    float* d = out + (size_t)e * NC;
    #pragma unroll
    for (int c = 0; c < NC; c++) d[c] = s[c];
}

// ================= host launcher =================
extern "C" void kernel_launch(void* const* d_in, const int* in_sizes, int n_in,
                              void* d_out, int out_size)
{
    const float* node_features = (const float*)d_in[0];
    const float* edge_features = (const float*)d_in[1];
    const int*   edge_index    = (const int*)d_in[2];
    const float* nw = (const float*)d_in[4];
    const float* nb = (const float*)d_in[5];
    const float* ew = (const float*)d_in[6];
    const float* eb = (const float*)d_in[7];
    const float* Wq = (const float*)d_in[8];  const float* bq = (const float*)d_in[9];
    const float* Wk = (const float*)d_in[10]; const float* bk = (const float*)d_in[11];
    const float* Wv = (const float*)d_in[12]; const float* bv = (const float*)d_in[13];
    const float* Wo = (const float*)d_in[14]; const float* bo = (const float*)d_in[15];
    const float* W1 = (const float*)d_in[16]; const float* b1 = (const float*)d_in[17];
    const float* W2 = (const float*)d_in[18]; const float* b2 = (const float*)d_in[19];
    float* out = (float*)d_out;
    const int* src = edge_index;
    const int* dst = edge_index + EE;

    float *qp, *kcp, *vcp, *efw1p, *aggp, *ntp, *nsp, *esp, *zbp;
    __nv_bfloat16 *whi, *wlo, *cefhi, *ceflo, *nfhi, *nflo, *aghi, *aglo, *awhi, *awlo;
    int *nlp;
    cudaGetSymbolAddress((void**)&qp,    g_q);
    cudaGetSymbolAddress((void**)&kcp,   g_kc);
    cudaGetSymbolAddress((void**)&vcp,   g_vc);
    cudaGetSymbolAddress((void**)&efw1p, g_efw1);
    cudaGetSymbolAddress((void**)&aggp,  g_agg);
    cudaGetSymbolAddress((void**)&ntp,   g_nt);
    cudaGetSymbolAddress((void**)&nsp,   g_nscore);
    cudaGetSymbolAddress((void**)&esp,   g_escore);
    cudaGetSymbolAddress((void**)&zbp,   g_zb);
    cudaGetSymbolAddress((void**)&whi,   g_whi);
    cudaGetSymbolAddress((void**)&wlo,   g_wlo);
    cudaGetSymbolAddress((void**)&cefhi, g_cefhi);
    cudaGetSymbolAddress((void**)&ceflo, g_ceflo);
    cudaGetSymbolAddress((void**)&nfhi,  g_nfhi);
    cudaGetSymbolAddress((void**)&nflo,  g_nflo);
    cudaGetSymbolAddress((void**)&aghi,  g_agghi);
    cudaGetSymbolAddress((void**)&aglo,  g_agglo);
    cudaGetSymbolAddress((void**)&awhi,  g_awhi);
    cudaGetSymbolAddress((void**)&awlo,  g_awlo);
    cudaGetSymbolAddress((void**)&nlp,   g_nlive);

    cudaFuncSetAttribute((const void*)mma_gemm<0>, cudaFuncAttributeMaxDynamicSharedMemorySize, GEMM_SMEM);
    cudaFuncSetAttribute((const void*)mma_gemm<4>, cudaFuncAttributeMaxDynamicSharedMemorySize, GEMM_SMEM);

    const size_t SB = (size_t)DE * DE;

    // 0. weight splits (1 kernel) + node-feature split
    wconv_all<<<(DE * DN + 4 * DE * DE + 255) / 256, 256>>>(Wq, Wk, Wv, Wo, W1);
    split_kernel<<<((size_t)NN * DN / 4 + 255) / 256, 256>>>(node_features, nfhi, nflo, (size_t)NN * DN / 4);
    zero_kernel<<<(NN + 255) / 256, 256>>>();

    // 1. exact fp32 scorers
    score_kernel<<<(NN + 7) / 8, 256>>>(node_features, nw, nb, nsp, NN, DN);
    score_kernel<<<(EE + 7) / 8, 256>>>(edge_features, ew, eb, esp, EE, DE);

    // 2. both top-k thresholds in one launch
    topk_kernel<<<2, 1024>>>();

    // 3. edge mask + degree counts + per-block live counts
    emask_count_kernel<<<625, 256>>>(src, dst);

    // 4. scans (compaction offsets + live CSR offsets)
    scan2_kernel<<<1, 1024>>>();

    // 5. order-preserving compaction + CSR scatter
    compact_kernel<<<625, 256>>>();
    csr_scatter_kernel<<<(MAXL + 255) / 256, 256>>>(src);

    // 6. gather + split live ef rows
    gather_split_kernel<<<2048, 256>>>(edge_features);

    // 7. GEMMs
    dim3 gq(4, (NN + 127) / 128);
    mma_gemm<0><<<gq, 256, GEMM_SMEM>>>(nfhi, nflo, whi + 0 * SB, wlo + 0 * SB, bq,
                                        qp, nullptr, nullptr, NN, DN, nullptr);
    dim3 gl(4, MAXL / 128);
    mma_gemm<0><<<gl, 256, GEMM_SMEM>>>(cefhi, ceflo, whi + 1 * SB, wlo + 1 * SB, bk,
                                        kcp, nullptr, nullptr, 0, DE, nlp);
    mma_gemm<0><<<gl, 256, GEMM_SMEM>>>(cefhi, ceflo, whi + 2 * SB, wlo + 2 * SB, bv,
                                        vcp, nullptr, nullptr, 0, DE, nlp);
    mma_gemm<0><<<gl, 256, GEMM_SMEM>>>(cefhi, ceflo, whi + 4 * SB, wlo + 4 * SB, zbp,
                                        efw1p, nullptr, nullptr, 0, DE, nlp);

    // 8. attention
    qbk_kernel<<<(NN + 7) / 8, 256>>>(bk);
    attn_live_kernel<<<(MAXL + 7) / 8, 256>>>(src);
    softmax_agg_kernel<<<NN, 256>>>(bv);

    // 9. node-side chain: agg -> aggWo (split out) -> nodeterm
    split_kernel<<<((size_t)NN * DE / 4 + 255) / 256, 256>>>(aggp, aghi, aglo, (size_t)NN * DE / 4);
    mma_gemm<4><<<gq, 256, GEMM_SMEM>>>(aghi, aglo, whi + 3 * SB, wlo + 3 * SB, bo,
                                        nullptr, awhi, awlo, NN, DE, nullptr);
    mma_gemm<0><<<gq, 256, GEMM_SMEM>>>(awhi, awlo, whi + 4 * SB, wlo + 4 * SB, b1,
                                        ntp, nullptr, nullptr, NN, DE, nullptr);

    // 10. outputs
    classify_node_kernel<<<(NN + 7) / 8, 256>>>(W2, b2);
    live_out_kernel<<<(MAXL + 7) / 8, 256>>>(src, W2, b2, out);
    dead_out_kernel<<<(EE + 255) / 256, 256>>>(src, out);
}